// round 1
// baseline (speedup 1.0000x reference)
#include <cuda_runtime.h>
#include <cstdint>

// ---------------- problem constants ----------------
#define NB    64      // batch
#define CIN   3
#define HIN   224
#define CH    96      // stem channels
#define HH    56      // stem output spatial
#define HO    14      // deform output spatial
#define SPA   196     // 14*14
#define MM2   12544   // 64*196  (GEMM M)
#define KDIM  1536    // 16*96   (GEMM K)
#define ND    768     // deform output channels
#define NOFF  32      // offset channels

// ---------------- scratch (device globals; no dynamic alloc allowed) -------
__device__ float g_h[(size_t)NB*HH*HH*CH];   // stem output, NHWC  (77 MB)
__device__ float g_buf[(size_t)MM2*KDIM];    // im2col / sampled matrix (77 MB)
__device__ float g_off[(size_t)MM2*NOFF];    // offsets, [m][32]
__device__ float g_wd[(size_t)ND*KDIM];      // dcn_w rearranged [o][k*96+c]
__device__ float g_wo[(size_t)NOFF*KDIM];    // off_w rearranged [o][k*96+c]

// =====================================================================
// Kernel 1: stem conv (4x4 stride 4, patchify) + BN1 + LeakyReLU -> NHWC
// block = (b, oh) row; 192 threads: o = tid%96, ow strided by 2
// =====================================================================
__global__ __launch_bounds__(192) void stem_kernel(
    const float* __restrict__ x, const float* __restrict__ w,
    const float* __restrict__ bias,
    const float* __restrict__ g1, const float* __restrict__ b1,
    const float* __restrict__ m1, const float* __restrict__ v1)
{
    int b  = blockIdx.x / HH;
    int oh = blockIdx.x % HH;
    __shared__ float sx[CIN*4*HIN];   // 2688 floats: [c*4+kh][224]
    __shared__ float sinv[CH], sbeta[CH];
    int tid = threadIdx.x;

    for (int i = tid; i < CIN*4*HIN; i += 192) {
        int j = i / HIN;          // c*4+kh
        int col = i % HIN;
        int c = j >> 2, kh = j & 3;
        sx[i] = x[((size_t)(b*CIN + c)*HIN + (4*oh + kh))*HIN + col];
    }
    if (tid < CH) {
        float inv = g1[tid] * rsqrtf(v1[tid] + 1e-5f);
        sinv[tid]  = inv;
        sbeta[tid] = (bias[tid] - m1[tid]) * inv + b1[tid];
    }
    __syncthreads();

    int o   = tid % CH;
    int owb = tid / CH;           // 0 or 1
    float4 wr[12];
    #pragma unroll
    for (int j = 0; j < 12; j++)
        wr[j] = *(const float4*)&w[o*48 + j*4];   // w[o][c][kh][kw], j=c*4+kh
    float inv = sinv[o], beta = sbeta[o];

    for (int ow = owb; ow < HH; ow += 2) {
        float acc = 0.f;
        #pragma unroll
        for (int j = 0; j < 12; j++) {
            float4 xv = *(const float4*)&sx[j*HIN + 4*ow];
            acc += xv.x*wr[j].x + xv.y*wr[j].y + xv.z*wr[j].z + xv.w*wr[j].w;
        }
        float val = acc*inv + beta;
        val = (val >= 0.f) ? val : 0.01f*val;
        g_h[((size_t)(b*HH + oh)*HH + ow)*CH + o] = val;
    }
}

// =====================================================================
// Kernel 2: rearrange weights [o][c*16+k] -> [o][k*96+c]
// =====================================================================
__global__ __launch_bounds__(256) void rearrange_kernel(
    const float* __restrict__ wd, const float* __restrict__ wo)
{
    int i = blockIdx.x*256 + threadIdx.x;
    if (i < ND*KDIM) {
        int o = i / KDIM, r = i % KDIM;
        int k = r / CH, c = r % CH;
        g_wd[i] = wd[(size_t)o*KDIM + c*16 + k];
    }
    if (i < NOFF*KDIM) {
        int o = i / KDIM, r = i % KDIM;
        int k = r / CH, c = r % CH;
        g_wo[i] = wo[(size_t)o*KDIM + c*16 + k];
    }
}

// =====================================================================
// Kernel 3: patchify h (integer grid, stride 4) -> g_buf[m][k*96+c]
// =====================================================================
__global__ __launch_bounds__(256) void patchify_kernel()
{
    int i = blockIdx.x*256 + threadIdx.x;        // one float4 each
    const int total = MM2*KDIM/4;
    if (i >= total) return;
    int e = i*4;
    int m = e / KDIM, r = e % KDIM;
    int k = r / CH,  c = r % CH;                 // c multiple of 4 (96%4==0)
    int b = m / SPA, s = m % SPA;
    int oh = s / HO, ow = s % HO;
    int y = oh*4 + (k >> 2);
    int xc = ow*4 + (k & 3);
    float4 v = *(const float4*)&g_h[((size_t)(b*HH + y)*HH + xc)*CH + c];
    *(float4*)&g_buf[(size_t)e] = v;
}

// =====================================================================
// Kernel 4: offset GEMM  C[12544][32] = A[12544][1536] * Wo^T + off_b
// block tile M=64, N=32, Kc=32; 256 threads; thread: 8 m-rows x 1 n
// =====================================================================
__global__ __launch_bounds__(256) void gemm_off_kernel(const float* __restrict__ offb)
{
    __shared__ float sA[32][64];
    __shared__ float sB[32][32];
    int tid = threadIdx.x;
    int bm = blockIdx.x * 64;
    int ty = tid >> 5, tx = tid & 31;

    float acc[8];
    #pragma unroll
    for (int i = 0; i < 8; i++) acc[i] = 0.f;

    int amr = tid >> 2;            // 0..63
    int akq = (tid & 3) * 8;       // 0,8,16,24
    int bnr = tid >> 3;            // 0..31
    int bkq = (tid & 7) * 4;       // 0..28
    const float* Ap = g_buf + (size_t)(bm + amr)*KDIM + akq;
    const float* Bp = g_wo  + (size_t)bnr*KDIM + bkq;

    for (int t = 0; t < KDIM/32; t++) {
        float4 a0 = *(const float4*)(Ap + t*32);
        float4 a1 = *(const float4*)(Ap + t*32 + 4);
        float4 b0 = *(const float4*)(Bp + t*32);
        __syncthreads();
        sA[akq+0][amr] = a0.x; sA[akq+1][amr] = a0.y;
        sA[akq+2][amr] = a0.z; sA[akq+3][amr] = a0.w;
        sA[akq+4][amr] = a1.x; sA[akq+5][amr] = a1.y;
        sA[akq+6][amr] = a1.z; sA[akq+7][amr] = a1.w;
        sB[bkq+0][bnr] = b0.x; sB[bkq+1][bnr] = b0.y;
        sB[bkq+2][bnr] = b0.z; sB[bkq+3][bnr] = b0.w;
        __syncthreads();
        #pragma unroll
        for (int kk = 0; kk < 32; kk++) {
            float bv = sB[kk][tx];
            float4 av0 = *(const float4*)&sA[kk][ty*8];
            float4 av1 = *(const float4*)&sA[kk][ty*8 + 4];
            acc[0] += av0.x*bv; acc[1] += av0.y*bv;
            acc[2] += av0.z*bv; acc[3] += av0.w*bv;
            acc[4] += av1.x*bv; acc[5] += av1.y*bv;
            acc[6] += av1.z*bv; acc[7] += av1.w*bv;
        }
    }
    float bb = offb[tx];
    #pragma unroll
    for (int i = 0; i < 8; i++)
        g_off[(size_t)(bm + ty*8 + i)*NOFF + tx] = acc[i] + bb;
}

// =====================================================================
// Kernel 5: bilinear sampling -> g_buf[m][k*96+c]
// one warp per (m, k); lanes over channels (coalesced NHWC gathers)
// =====================================================================
__global__ __launch_bounds__(256) void sample_kernel()
{
    int gw   = (blockIdx.x*256 + threadIdx.x) >> 5;
    int lane = threadIdx.x & 31;
    if (gw >= MM2*16) return;
    int m = gw >> 4, k = gw & 15;
    int b = m / SPA, s = m % SPA;
    int oh = s / HO, ow = s % HO;

    float offy = g_off[(size_t)m*NOFF + k*2];
    float offx = g_off[(size_t)m*NOFF + k*2 + 1];
    float py = (float)(oh*4 + (k >> 2)) + offy;
    float px = (float)(ow*4 + (k & 3)) + offx;
    float y0f = floorf(py), x0f = floorf(px);
    float wy = py - y0f, wx = px - x0f;
    int y0 = (int)y0f, x0 = (int)x0f;
    int y1 = y0 + 1,  x1 = x0 + 1;
    bool vy0 = (y0 >= 0) & (y0 < HH), vy1 = (y1 >= 0) & (y1 < HH);
    bool vx0 = (x0 >= 0) & (x0 < HH), vx1 = (x1 >= 0) & (x1 < HH);
    int cy0 = min(max(y0, 0), HH-1), cy1 = min(max(y1, 0), HH-1);
    int cx0 = min(max(x0, 0), HH-1), cx1 = min(max(x1, 0), HH-1);

    const float* hb = g_h + (size_t)b*HH*HH*CH;
    const float* p00 = hb + (size_t)(cy0*HH + cx0)*CH;
    const float* p01 = hb + (size_t)(cy0*HH + cx1)*CH;
    const float* p10 = hb + (size_t)(cy1*HH + cx0)*CH;
    const float* p11 = hb + (size_t)(cy1*HH + cx1)*CH;

    float w00 = (1.f-wy)*(1.f-wx) * (float)(vy0 && vx0);
    float w01 = (1.f-wy)*wx       * (float)(vy0 && vx1);
    float w10 = wy*(1.f-wx)       * (float)(vy1 && vx0);
    float w11 = wy*wx             * (float)(vy1 && vx1);

    float* outp = g_buf + (size_t)m*KDIM + k*CH;
    #pragma unroll
    for (int cg = 0; cg < 3; cg++) {
        int c = cg*32 + lane;
        float v = p00[c]*w00 + p01[c]*w01 + p10[c]*w10 + p11[c]*w11;
        outp[c] = v;
    }
}

// =====================================================================
// Kernel 6: deform GEMM  M=12544, N=768, K=1536  + BN2 + LeakyReLU
// 128x128 tile, K-step 8, 256 threads, 8x8 per thread, double-buffered
// Output written directly in final (B, HoWo, C) layout.
// =====================================================================
__global__ __launch_bounds__(256, 2) void gemm_big_kernel(
    const float* __restrict__ dcnb, const float* __restrict__ g2,
    const float* __restrict__ b2,   const float* __restrict__ bn2m,
    const float* __restrict__ v2,   float* __restrict__ out)
{
    __shared__ float sA[2][8][128];
    __shared__ float sB[2][8][128];
    __shared__ float sScale[128], sBeta[128];

    int tid = threadIdx.x;
    int bm = blockIdx.y * 128;
    int bn = blockIdx.x * 128;

    if (tid < 128) {
        int n = bn + tid;
        float inv = g2[n] * rsqrtf(v2[n] + 1e-5f);
        sScale[tid] = inv;
        sBeta[tid]  = (dcnb[n] - bn2m[n])*inv + b2[n];
    }

    int lr = tid >> 1;             // 0..127
    int lk = (tid & 1) * 4;        // 0 or 4
    const float* Aptr = g_buf + (size_t)(bm + lr)*KDIM + lk;
    const float* Bptr = g_wd  + (size_t)(bn + lr)*KDIM + lk;

    float acc[8][8];
    #pragma unroll
    for (int i = 0; i < 8; i++)
        #pragma unroll
        for (int j = 0; j < 8; j++) acc[i][j] = 0.f;

    {   // preload tile 0
        float4 av = *(const float4*)Aptr;
        float4 bv = *(const float4*)Bptr;
        sA[0][lk+0][lr] = av.x; sA[0][lk+1][lr] = av.y;
        sA[0][lk+2][lr] = av.z; sA[0][lk+3][lr] = av.w;
        sB[0][lk+0][lr] = bv.x; sB[0][lk+1][lr] = bv.y;
        sB[0][lk+2][lr] = bv.z; sB[0][lk+3][lr] = bv.w;
    }
    __syncthreads();

    int ty = tid >> 4, tx = tid & 15;
    int cur = 0;
    const int NT = KDIM/8;   // 192

    for (int t = 0; t < NT; t++) {
        float4 an, bv;
        if (t + 1 < NT) {
            an = *(const float4*)(Aptr + (t+1)*8);
            bv = *(const float4*)(Bptr + (t+1)*8);
        }
        #pragma unroll
        for (int kk = 0; kk < 8; kk++) {
            float4 a0 = *(const float4*)&sA[cur][kk][ty*4];
            float4 a1 = *(const float4*)&sA[cur][kk][64 + ty*4];
            float4 b0 = *(const float4*)&sB[cur][kk][tx*4];
            float4 b1 = *(const float4*)&sB[cur][kk][64 + tx*4];
            float a[8] = {a0.x,a0.y,a0.z,a0.w,a1.x,a1.y,a1.z,a1.w};
            float bb[8] = {b0.x,b0.y,b0.z,b0.w,b1.x,b1.y,b1.z,b1.w};
            #pragma unroll
            for (int i = 0; i < 8; i++)
                #pragma unroll
                for (int j = 0; j < 8; j++)
                    acc[i][j] += a[i]*bb[j];
        }
        if (t + 1 < NT) {
            int nxt = cur ^ 1;
            sA[nxt][lk+0][lr] = an.x; sA[nxt][lk+1][lr] = an.y;
            sA[nxt][lk+2][lr] = an.z; sA[nxt][lk+3][lr] = an.w;
            sB[nxt][lk+0][lr] = bv.x; sB[nxt][lk+1][lr] = bv.y;
            sB[nxt][lk+2][lr] = bv.z; sB[nxt][lk+3][lr] = bv.w;
            __syncthreads();
            cur = nxt;
        }
    }

    // epilogue: BN2 + LeakyReLU, write final layout
    #pragma unroll
    for (int i = 0; i < 8; i++) {
        int mrow = bm + ((i < 4) ? (ty*4 + i) : (64 + ty*4 + i - 4));
        float4 o0, o1;
        float* po0 = &o0.x;
        float* po1 = &o1.x;
        #pragma unroll
        for (int j = 0; j < 4; j++) {
            int n0 = tx*4 + j;
            float v = acc[i][j]*sScale[n0] + sBeta[n0];
            po0[j] = (v >= 0.f) ? v : 0.01f*v;
            int n1 = 64 + tx*4 + j;
            float w = acc[i][4+j]*sScale[n1] + sBeta[n1];
            po1[j] = (w >= 0.f) ? w : 0.01f*w;
        }
        *(float4*)&out[(size_t)mrow*ND + bn + tx*4]      = o0;
        *(float4*)&out[(size_t)mrow*ND + bn + 64 + tx*4] = o1;
    }
}

// =====================================================================
extern "C" void kernel_launch(void* const* d_in, const int* in_sizes, int n_in,
                              void* d_out, int out_size)
{
    const float* x      = (const float*)d_in[0];
    const float* stem_w = (const float*)d_in[1];
    const float* stem_b = (const float*)d_in[2];
    const float* bn1_g  = (const float*)d_in[3];
    const float* bn1_b  = (const float*)d_in[4];
    const float* bn1_m  = (const float*)d_in[5];
    const float* bn1_v  = (const float*)d_in[6];
    const float* off_w  = (const float*)d_in[7];
    const float* off_b  = (const float*)d_in[8];
    const float* dcn_w  = (const float*)d_in[9];
    const float* dcn_b  = (const float*)d_in[10];
    const float* bn2_g  = (const float*)d_in[11];
    const float* bn2_b  = (const float*)d_in[12];
    const float* bn2_m  = (const float*)d_in[13];
    const float* bn2_v  = (const float*)d_in[14];
    float* out = (float*)d_out;

    stem_kernel<<<NB*HH, 192>>>(x, stem_w, stem_b, bn1_g, bn1_b, bn1_m, bn1_v);
    rearrange_kernel<<<(ND*KDIM + 255)/256, 256>>>(dcn_w, off_w);
    patchify_kernel<<<(MM2*KDIM/4 + 255)/256, 256>>>();
    gemm_off_kernel<<<MM2/64, 256>>>(off_b);
    sample_kernel<<<(MM2*16*32)/256, 256>>>();
    gemm_big_kernel<<<dim3(ND/128, MM2/128), 256>>>(dcn_b, bn2_g, bn2_b, bn2_m, bn2_v, out);
}

// round 3
// speedup vs baseline: 1.5256x; 1.5256x over previous
#include <cuda_runtime.h>
#include <cuda_bf16.h>
#include <cstdint>

// ---------------- problem constants ----------------
#define NB    64
#define CIN   3
#define HIN   224
#define CH    96
#define HH    56
#define HO    14
#define SPA   196
#define MM2   12544   // GEMM M
#define KDIM  1536    // GEMM K
#define ND    768     // GEMM N
#define NOFF  32

// ---------------- scratch (device globals) ----------------
__device__ float         g_h[(size_t)NB*HH*HH*CH];    // stem output NHWC
__device__ float         g_off[(size_t)MM2*NOFF];     // offsets [m][32]
__device__ float         g_wo2[(size_t)16*CH*NOFF];   // off_w as [kpix][c][n]
__device__ __nv_bfloat16 g_Ahi[(size_t)MM2*KDIM];
__device__ __nv_bfloat16 g_Alo[(size_t)MM2*KDIM];
__device__ __nv_bfloat16 g_Bhi[(size_t)ND*KDIM];
__device__ __nv_bfloat16 g_Blo[(size_t)ND*KDIM];

// ==================== PTX helpers (plain-target safe) ====================
__device__ __forceinline__ uint32_t smem_to_u32(const void* p) {
    uint32_t a;
    asm("{ .reg .u64 t; cvta.to.shared.u64 t, %1; cvt.u32.u64 %0, t; }" : "=r"(a) : "l"(p));
    return a;
}
#define CP_ASYNC16(s, g) \
    asm volatile("cp.async.cg.shared.global [%0], [%1], 16;" :: "r"(s), "l"(g) : "memory")
#define CP_COMMIT() asm volatile("cp.async.commit_group;" ::: "memory")
#define LDSM4(r, a) \
    asm volatile("ldmatrix.sync.aligned.m8n8.x4.shared.b16 {%0,%1,%2,%3}, [%4];" \
        : "=r"((r)[0]), "=r"((r)[1]), "=r"((r)[2]), "=r"((r)[3]) : "r"(a))
#define MMA16816(d, a, b0v, b1v) \
    asm volatile("mma.sync.aligned.m16n8k16.row.col.f32.bf16.bf16.f32 " \
        "{%0,%1,%2,%3},{%4,%5,%6,%7},{%8,%9},{%0,%1,%2,%3};" \
        : "+f"((d)[0]), "+f"((d)[1]), "+f"((d)[2]), "+f"((d)[3]) \
        : "r"((a)[0]), "r"((a)[1]), "r"((a)[2]), "r"((a)[3]), "r"(b0v), "r"(b1v))

// =====================================================================
// Kernel 1: stem conv + BN1 + LeakyReLU -> g_h (NHWC)
// =====================================================================
__global__ __launch_bounds__(192) void stem_kernel(
    const float* __restrict__ x, const float* __restrict__ w,
    const float* __restrict__ bias,
    const float* __restrict__ g1, const float* __restrict__ b1,
    const float* __restrict__ m1, const float* __restrict__ v1)
{
    int b  = blockIdx.x / HH;
    int oh = blockIdx.x % HH;
    __shared__ float sx[CIN*4*HIN];
    __shared__ float sinv[CH], sbeta[CH];
    int tid = threadIdx.x;

    for (int i = tid; i < CIN*4*HIN; i += 192) {
        int j = i / HIN, col = i % HIN;
        int c = j >> 2, kh = j & 3;
        sx[i] = x[((size_t)(b*CIN + c)*HIN + (4*oh + kh))*HIN + col];
    }
    if (tid < CH) {
        float inv = g1[tid] * rsqrtf(v1[tid] + 1e-5f);
        sinv[tid]  = inv;
        sbeta[tid] = (bias[tid] - m1[tid]) * inv + b1[tid];
    }
    __syncthreads();

    int o = tid % CH, owb = tid / CH;
    float4 wr[12];
    #pragma unroll
    for (int j = 0; j < 12; j++) wr[j] = *(const float4*)&w[o*48 + j*4];
    float inv = sinv[o], beta = sbeta[o];

    for (int ow = owb; ow < HH; ow += 2) {
        float acc = 0.f;
        #pragma unroll
        for (int j = 0; j < 12; j++) {
            float4 xv = *(const float4*)&sx[j*HIN + 4*ow];
            acc += xv.x*wr[j].x + xv.y*wr[j].y + xv.z*wr[j].z + xv.w*wr[j].w;
        }
        float val = acc*inv + beta;
        val = (val >= 0.f) ? val : 0.01f*val;
        g_h[((size_t)(b*HH + oh)*HH + ow)*CH + o] = val;
    }
}

// =====================================================================
// Kernel 2: weight prep: dcn_w -> bf16 hi/lo [o][k*96+c]; off_w -> [kpix][c][n]
// =====================================================================
__global__ __launch_bounds__(256) void prep_kernel(
    const float* __restrict__ wd, const float* __restrict__ wo)
{
    int i = blockIdx.x*256 + threadIdx.x;
    if (i < ND*KDIM) {
        int o = i / KDIM, r = i % KDIM;
        int k = r / CH, c = r % CH;
        float v = wd[(size_t)o*KDIM + c*16 + k];
        __nv_bfloat16 hi = __float2bfloat16(v);
        g_Bhi[i] = hi;
        g_Blo[i] = __float2bfloat16(v - __bfloat162float(hi));
    }
    if (i < 16*CH*NOFF) {
        int kp = i / (CH*NOFF), r = i % (CH*NOFF);
        g_wo2[i] = wo[(size_t)(r % NOFF)*KDIM + (r / NOFF)*16 + kp];
    }
}

// =====================================================================
// Kernel 3: offset conv directly from g_h (16 patches per block)
// =====================================================================
__global__ __launch_bounds__(256) void offconv_kernel(const float* __restrict__ offb)
{
    __shared__ float sA[16][CH];
    __shared__ float sB[CH][NOFF];
    int tid = threadIdx.x;
    int bm = blockIdx.x * 16;
    int n = tid & 31, rp = tid >> 5;
    float acc0 = 0.f, acc1 = 0.f;

    for (int kp = 0; kp < 16; kp++) {
        __syncthreads();
        for (int i = tid; i < 16*CH; i += 256) {
            int r = i / CH, c = i % CH;
            int m = bm + r, b = m / SPA, s = m % SPA;
            int oh = s / HO, ow = s % HO;
            int y = oh*4 + (kp >> 2), xx = ow*4 + (kp & 3);
            sA[r][c] = g_h[((size_t)(b*HH + y)*HH + xx)*CH + c];
        }
        for (int i = tid; i < CH*NOFF; i += 256)
            sB[i >> 5][i & 31] = g_wo2[kp*CH*NOFF + i];
        __syncthreads();
        #pragma unroll 8
        for (int kk = 0; kk < CH; kk++) {
            float bv = sB[kk][n];
            acc0 += sA[rp][kk]     * bv;
            acc1 += sA[rp + 8][kk] * bv;
        }
    }
    float bb = offb[n];
    g_off[(size_t)(bm + rp)*NOFF + n]     = acc0 + bb;
    g_off[(size_t)(bm + rp + 8)*NOFF + n] = acc1 + bb;
}

// =====================================================================
// Kernel 4: bilinear sampling -> bf16 hi/lo A matrix [m][k*96+c]
// =====================================================================
__global__ __launch_bounds__(256) void sample_kernel()
{
    int gw   = (blockIdx.x*256 + threadIdx.x) >> 5;
    int lane = threadIdx.x & 31;
    if (gw >= MM2*16) return;
    int m = gw >> 4, k = gw & 15;
    int b = m / SPA, s = m % SPA;
    int oh = s / HO, ow = s % HO;

    float offy = g_off[(size_t)m*NOFF + k*2];
    float offx = g_off[(size_t)m*NOFF + k*2 + 1];
    float py = (float)(oh*4 + (k >> 2)) + offy;
    float px = (float)(ow*4 + (k & 3)) + offx;
    float y0f = floorf(py), x0f = floorf(px);
    float wy = py - y0f, wx = px - x0f;
    int y0 = (int)y0f, x0 = (int)x0f;
    int y1 = y0 + 1,  x1 = x0 + 1;
    bool vy0 = (y0 >= 0) & (y0 < HH), vy1 = (y1 >= 0) & (y1 < HH);
    bool vx0 = (x0 >= 0) & (x0 < HH), vx1 = (x1 >= 0) & (x1 < HH);
    int cy0 = min(max(y0, 0), HH-1), cy1 = min(max(y1, 0), HH-1);
    int cx0 = min(max(x0, 0), HH-1), cx1 = min(max(x1, 0), HH-1);

    const float* hb = g_h + (size_t)b*HH*HH*CH;
    const float* p00 = hb + (size_t)(cy0*HH + cx0)*CH;
    const float* p01 = hb + (size_t)(cy0*HH + cx1)*CH;
    const float* p10 = hb + (size_t)(cy1*HH + cx0)*CH;
    const float* p11 = hb + (size_t)(cy1*HH + cx1)*CH;

    float w00 = (1.f-wy)*(1.f-wx) * (float)(vy0 && vx0);
    float w01 = (1.f-wy)*wx       * (float)(vy0 && vx1);
    float w10 = wy*(1.f-wx)       * (float)(vy1 && vx0);
    float w11 = wy*wx             * (float)(vy1 && vx1);

    size_t base = (size_t)m*KDIM + k*CH;
    #pragma unroll
    for (int cg = 0; cg < 3; cg++) {
        int c = cg*32 + lane;
        float v = p00[c]*w00 + p01[c]*w01 + p10[c]*w10 + p11[c]*w11;
        __nv_bfloat16 hi = __float2bfloat16(v);
        g_Ahi[base + c] = hi;
        g_Alo[base + c] = __float2bfloat16(v - __bfloat162float(hi));
    }
}

// =====================================================================
// Kernel 5: mma.sync bf16 split GEMM: out = A*B^T (+BN2+LeakyReLU)
// CTA tile 128x256, BK=32, 8 warps (warp tile 64x64), 3-stage cp.async.
// D += Ahi*Bhi + Ahi*Blo + Alo*Bhi  (fp32-class accuracy)
// SMEM stage layout: [Ahi 8K][Alo 8K][Bhi 16K][Blo 16K]; swizzle c^=(row>>1)&3
// =====================================================================
#define BK       32
#define NIT      48           // 1536/32
#define STG_A    8192u
#define STG_B    16384u
#define STG_BYTES 49152u
#define NSTAGE   3
#define SMEM_GEMM (NSTAGE*STG_BYTES + 2048)

__global__ __launch_bounds__(256, 1) void gemm_mma_kernel(
    const float* __restrict__ dcnb, const float* __restrict__ g2,
    const float* __restrict__ b2,   const float* __restrict__ bn2m,
    const float* __restrict__ v2,   float* __restrict__ out)
{
    extern __shared__ char smem[];
    uint32_t sb = smem_to_u32(smem);
    float* sScale = (float*)(smem + NSTAGE*STG_BYTES);
    float* sBeta  = (float*)(smem + NSTAGE*STG_BYTES + 1024);

    int tid  = threadIdx.x;
    int lane = tid & 31, wid = tid >> 5;
    int wm = wid & 1, wn = wid >> 1;        // 2 x 4 warp grid
    int bm = blockIdx.y * 128;
    int bn = blockIdx.x * 256;

    {   // BN constants for this CTA's 256 output channels
        int n = bn + tid;
        float inv = g2[n] * rsqrtf(v2[n] + 1e-5f);
        sScale[tid] = inv;
        sBeta[tid]  = (dcnb[n] - bn2m[n])*inv + b2[n];
    }

    // ---- stage loader: 3072 x 16B chunks, 12 per thread ----
    auto load_stage = [&](int stg, int kt) {
        uint32_t base = sb + (uint32_t)stg * STG_BYTES;
        int ks = kt * BK;
        #pragma unroll
        for (int i = 0; i < 2; i++) {             // A hi+lo: 512 chunks each
            int id = tid + i*256;
            int row = id >> 2, c = id & 3;
            uint32_t so = (uint32_t)(row*64 + ((c ^ ((row >> 1) & 3)) * 16));
            size_t gi = (size_t)(bm + row)*KDIM + ks + c*8;
            CP_ASYNC16(base + so,         g_Ahi + gi);
            CP_ASYNC16(base + STG_A + so, g_Alo + gi);
        }
        #pragma unroll
        for (int i = 0; i < 4; i++) {             // B hi+lo: 1024 chunks each
            int id = tid + i*256;
            int row = id >> 2, c = id & 3;
            uint32_t so = (uint32_t)(row*64 + ((c ^ ((row >> 1) & 3)) * 16));
            size_t gi = (size_t)(bn + row)*KDIM + ks + c*8;
            CP_ASYNC16(base + 2*STG_A + so,         g_Bhi + gi);
            CP_ASYNC16(base + 2*STG_A + STG_B + so, g_Blo + gi);
        }
        CP_COMMIT();
    };

    // ---- per-thread ldmatrix offsets (tile-local) ----
    int lrow = lane & 15, lc = lane >> 4;
    uint32_t a_off[4][2], b_off[4][2];
    #pragma unroll
    for (int mi = 0; mi < 4; mi++) {
        int row = wm*64 + mi*16 + lrow;
        int rs = (row >> 1) & 3;
        #pragma unroll
        for (int kh = 0; kh < 2; kh++)
            a_off[mi][kh] = (uint32_t)(row*64 + (((kh*2 + lc) ^ rs) * 16));
    }
    #pragma unroll
    for (int nb = 0; nb < 4; nb++) {
        int row = wn*64 + nb*16 + lrow;
        int rs = (row >> 1) & 3;
        #pragma unroll
        for (int kh = 0; kh < 2; kh++)
            b_off[nb][kh] = (uint32_t)(row*64 + (((kh*2 + lc) ^ rs) * 16));
    }

    float acc[4][8][4];
    #pragma unroll
    for (int i = 0; i < 4; i++)
        #pragma unroll
        for (int j = 0; j < 8; j++)
            #pragma unroll
            for (int q = 0; q < 4; q++) acc[i][j][q] = 0.f;

    load_stage(0, 0);
    load_stage(1, 1);

    for (int kt = 0; kt < NIT; kt++) {
        if (kt == NIT-1) asm volatile("cp.async.wait_group 0;" ::: "memory");
        else             asm volatile("cp.async.wait_group 1;" ::: "memory");
        __syncthreads();
        if (kt + 2 < NIT) load_stage((kt+2) % NSTAGE, kt+2);

        uint32_t base = sb + (uint32_t)(kt % NSTAGE) * STG_BYTES;
        #pragma unroll
        for (int kh = 0; kh < 2; kh++) {
            uint32_t ah[4][4], al[4][4];
            #pragma unroll
            for (int mi = 0; mi < 4; mi++) {
                LDSM4(ah[mi], base + a_off[mi][kh]);
                LDSM4(al[mi], base + STG_A + a_off[mi][kh]);
            }
            #pragma unroll
            for (int nb = 0; nb < 4; nb++) {
                uint32_t bh[4], bl[4];
                LDSM4(bh, base + 2*STG_A + b_off[nb][kh]);
                LDSM4(bl, base + 2*STG_A + STG_B + b_off[nb][kh]);
                #pragma unroll
                for (int mi = 0; mi < 4; mi++) {
                    MMA16816(acc[mi][2*nb],   ah[mi], bh[0], bh[2]);
                    MMA16816(acc[mi][2*nb+1], ah[mi], bh[1], bh[3]);
                    MMA16816(acc[mi][2*nb],   ah[mi], bl[0], bl[2]);
                    MMA16816(acc[mi][2*nb+1], ah[mi], bl[1], bl[3]);
                    MMA16816(acc[mi][2*nb],   al[mi], bh[0], bh[2]);
                    MMA16816(acc[mi][2*nb+1], al[mi], bh[1], bh[3]);
                }
            }
        }
    }

    // ---- epilogue: BN2 + LeakyReLU, write final (B, HoWo, C) layout ----
    #pragma unroll
    for (int mi = 0; mi < 4; mi++) {
        int r0 = bm + wm*64 + mi*16 + (lane >> 2);
        #pragma unroll
        for (int nj = 0; nj < 8; nj++) {
            int colL = wn*64 + nj*8 + (lane & 3)*2;
            float s0 = sScale[colL],   s1 = sScale[colL+1];
            float e0 = sBeta[colL],    e1 = sBeta[colL+1];
            float v0 = acc[mi][nj][0]*s0 + e0;
            float v1 = acc[mi][nj][1]*s1 + e1;
            float v2 = acc[mi][nj][2]*s0 + e0;
            float v3 = acc[mi][nj][3]*s1 + e1;
            v0 = (v0 >= 0.f) ? v0 : 0.01f*v0;
            v1 = (v1 >= 0.f) ? v1 : 0.01f*v1;
            v2 = (v2 >= 0.f) ? v2 : 0.01f*v2;
            v3 = (v3 >= 0.f) ? v3 : 0.01f*v3;
            *(float2*)&out[(size_t)r0*ND + bn + colL]     = make_float2(v0, v1);
            *(float2*)&out[(size_t)(r0+8)*ND + bn + colL] = make_float2(v2, v3);
        }
    }
}

// =====================================================================
extern "C" void kernel_launch(void* const* d_in, const int* in_sizes, int n_in,
                              void* d_out, int out_size)
{
    const float* x      = (const float*)d_in[0];
    const float* stem_w = (const float*)d_in[1];
    const float* stem_b = (const float*)d_in[2];
    const float* bn1_g  = (const float*)d_in[3];
    const float* bn1_b  = (const float*)d_in[4];
    const float* bn1_m  = (const float*)d_in[5];
    const float* bn1_v  = (const float*)d_in[6];
    const float* off_w  = (const float*)d_in[7];
    const float* off_b  = (const float*)d_in[8];
    const float* dcn_w  = (const float*)d_in[9];
    const float* dcn_b  = (const float*)d_in[10];
    const float* bn2_g  = (const float*)d_in[11];
    const float* bn2_b  = (const float*)d_in[12];
    const float* bn2_m  = (const float*)d_in[13];
    const float* bn2_v  = (const float*)d_in[14];
    float* out = (float*)d_out;

    cudaFuncSetAttribute(gemm_mma_kernel,
                         cudaFuncAttributeMaxDynamicSharedMemorySize, SMEM_GEMM);

    stem_kernel<<<NB*HH, 192>>>(x, stem_w, stem_b, bn1_g, bn1_b, bn1_m, bn1_v);
    prep_kernel<<<(ND*KDIM + 255)/256, 256>>>(dcn_w, off_w);
    offconv_kernel<<<MM2/16, 256>>>(off_b);
    sample_kernel<<<(MM2*16*32)/256, 256>>>();
    gemm_mma_kernel<<<dim3(ND/256, MM2/128), 256, SMEM_GEMM>>>(
        dcn_b, bn2_g, bn2_b, bn2_m, bn2_v, out);
}

// round 4
// speedup vs baseline: 2.3617x; 1.5481x over previous
#include <cuda_runtime.h>
#include <cuda_fp16.h>
#include <cstdint>

// ---------------- problem constants ----------------
#define NB    64
#define CIN   3
#define HIN   224
#define CH    96
#define HH    56
#define HO    14
#define SPA   196
#define MM2   12544   // GEMM M
#define KDIM  1536    // GEMM K
#define ND    768     // GEMM N
#define NOFF  32

// ---------------- scratch (device globals) ----------------
__device__ float  g_h [(size_t)NB*HH*HH*CH];   // stem output NHWC fp32 (sampler)
__device__ __half g_hh[(size_t)NB*HH*HH*CH];   // stem output fp16 hi (offconv)
__device__ __half g_hl[(size_t)NB*HH*HH*CH];   // stem output fp16 lo (offconv)
__device__ float  g_off[(size_t)MM2*NOFF];     // offsets [m][32]
__device__ __half g_woh[(size_t)NOFF*KDIM];    // off_w [n][k*96+c] fp16 hi
__device__ __half g_wol[(size_t)NOFF*KDIM];    // off_w fp16 lo
__device__ __half g_Af [(size_t)MM2*KDIM];     // sampled A, plain fp16
__device__ __half g_Bhi[(size_t)ND*KDIM];      // dcn_w [o][k*96+c] fp16 hi
__device__ __half g_Blo[(size_t)ND*KDIM];      // dcn_w fp16 lo

// ==================== PTX helpers (plain-target safe) ====================
__device__ __forceinline__ uint32_t smem_to_u32(const void* p) {
    uint32_t a;
    asm("{ .reg .u64 t; cvta.to.shared.u64 t, %1; cvt.u32.u64 %0, t; }" : "=r"(a) : "l"(p));
    return a;
}
#define CP_ASYNC16(s, g) \
    asm volatile("cp.async.cg.shared.global [%0], [%1], 16;" :: "r"(s), "l"(g) : "memory")
#define CP_COMMIT() asm volatile("cp.async.commit_group;" ::: "memory")
#define LDSM4(r, a) \
    asm volatile("ldmatrix.sync.aligned.m8n8.x4.shared.b16 {%0,%1,%2,%3}, [%4];" \
        : "=r"((r)[0]), "=r"((r)[1]), "=r"((r)[2]), "=r"((r)[3]) : "r"(a))
#define MMA16816(d, a, b0v, b1v) \
    asm volatile("mma.sync.aligned.m16n8k16.row.col.f32.f16.f16.f32 " \
        "{%0,%1,%2,%3},{%4,%5,%6,%7},{%8,%9},{%0,%1,%2,%3};" \
        : "+f"((d)[0]), "+f"((d)[1]), "+f"((d)[2]), "+f"((d)[3]) \
        : "r"((a)[0]), "r"((a)[1]), "r"((a)[2]), "r"((a)[3]), "r"(b0v), "r"(b1v))

// =====================================================================
// Kernel 1: stem conv + BN1 + LeakyReLU -> g_h fp32 + g_hh/g_hl fp16
// =====================================================================
__global__ __launch_bounds__(192) void stem_kernel(
    const float* __restrict__ x, const float* __restrict__ w,
    const float* __restrict__ bias,
    const float* __restrict__ g1, const float* __restrict__ b1,
    const float* __restrict__ m1, const float* __restrict__ v1)
{
    int b  = blockIdx.x / HH;
    int oh = blockIdx.x % HH;
    __shared__ float sx[CIN*4*HIN];
    __shared__ float sinv[CH], sbeta[CH];
    int tid = threadIdx.x;

    for (int i = tid; i < CIN*4*HIN; i += 192) {
        int j = i / HIN, col = i % HIN;
        int c = j >> 2, kh = j & 3;
        sx[i] = x[((size_t)(b*CIN + c)*HIN + (4*oh + kh))*HIN + col];
    }
    if (tid < CH) {
        float inv = g1[tid] * rsqrtf(v1[tid] + 1e-5f);
        sinv[tid]  = inv;
        sbeta[tid] = (bias[tid] - m1[tid]) * inv + b1[tid];
    }
    __syncthreads();

    int o = tid % CH, owb = tid / CH;
    float4 wr[12];
    #pragma unroll
    for (int j = 0; j < 12; j++) wr[j] = *(const float4*)&w[o*48 + j*4];
    float inv = sinv[o], beta = sbeta[o];

    for (int ow = owb; ow < HH; ow += 2) {
        float acc = 0.f;
        #pragma unroll
        for (int j = 0; j < 12; j++) {
            float4 xv = *(const float4*)&sx[j*HIN + 4*ow];
            acc += xv.x*wr[j].x + xv.y*wr[j].y + xv.z*wr[j].z + xv.w*wr[j].w;
        }
        float val = acc*inv + beta;
        val = (val >= 0.f) ? val : 0.01f*val;
        size_t idx = ((size_t)(b*HH + oh)*HH + ow)*CH + o;
        g_h[idx] = val;
        __half hv = __float2half(val);
        g_hh[idx] = hv;
        g_hl[idx] = __float2half(val - __half2float(hv));
    }
}

// =====================================================================
// Kernel 2: weight prep (dcn_w hi/lo, off_w hi/lo, both [n][k*96+c])
// =====================================================================
__global__ __launch_bounds__(256) void prep_kernel(
    const float* __restrict__ wd, const float* __restrict__ wo)
{
    int i = blockIdx.x*256 + threadIdx.x;
    if (i < ND*KDIM) {
        int o = i / KDIM, r = i % KDIM;
        int k = r / CH, c = r % CH;
        float v = wd[(size_t)o*KDIM + c*16 + k];
        __half hi = __float2half(v);
        g_Bhi[i] = hi;
        g_Blo[i] = __float2half(v - __half2float(hi));
    }
    if (i < NOFF*KDIM) {
        int n = i / KDIM, r = i % KDIM;
        int k = r / CH, c = r % CH;
        float v = wo[(size_t)n*KDIM + c*16 + k];
        __half hi = __float2half(v);
        g_woh[i] = hi;
        g_wol[i] = __float2half(v - __half2float(hi));
    }
}

// =====================================================================
// Kernel 3: offset conv via mma.sync, 3-pass fp16 hi/lo (exact offsets)
// M-tile 64, N=32, BK=32, 4 warps, 4-stage cp.async, im2col on the fly
// =====================================================================
#define OC_NIT 48
#define OC_STG 12288u    // Ah 4K | Al 4K | Wh 2K | Wl 2K
#define SMEM_OC (4*OC_STG)

__global__ __launch_bounds__(128, 1) void offconv_mma_kernel(const float* __restrict__ offb)
{
    extern __shared__ char smem[];
    uint32_t sb = smem_to_u32(smem);
    int tid = threadIdx.x;
    int lane = tid & 31, wid = tid >> 5;
    int bm = blockIdx.x * 64;

    // ---- loader precompute: rows r0 = tid>>2, r1 = r0+32 (fixed) ----
    int c4 = tid & 3;
    int r0 = tid >> 2, r1 = r0 + 32;
    int m0 = bm + r0, m1v = bm + r1;
    int b0 = m0 / SPA, s0 = m0 % SPA;
    int b1 = m1v / SPA, s1 = m1v % SPA;
    size_t rb0 = ((size_t)(b0*HH + (s0/HO)*4)*HH + (s0%HO)*4)*CH;
    size_t rb1 = ((size_t)(b1*HH + (s1/HO)*4)*HH + (s1%HO)*4)*CH;
    uint32_t so0 = (uint32_t)(r0*64 + ((c4 ^ ((r0>>1)&3))*16));
    uint32_t so1 = (uint32_t)(r1*64 + ((c4 ^ ((r1>>1)&3))*16));
    int wrow = tid >> 2;                          // 0..31
    uint32_t sow = (uint32_t)(wrow*64 + ((c4 ^ ((wrow>>1)&3))*16));
    size_t wg = (size_t)wrow*KDIM + c4*8;

    auto load_stage = [&](int stg, int kt) {
        uint32_t base = sb + (uint32_t)stg * OC_STG;
        int kpix = kt / 3;
        int poff = (kpix >> 2)*(HH*CH) + (kpix & 3)*CH + (kt - kpix*3)*32 + c4*8;
        CP_ASYNC16(base + so0,         g_hh + rb0 + poff);
        CP_ASYNC16(base + 4096 + so0,  g_hl + rb0 + poff);
        CP_ASYNC16(base + so1,         g_hh + rb1 + poff);
        CP_ASYNC16(base + 4096 + so1,  g_hl + rb1 + poff);
        CP_ASYNC16(base + 8192 + sow,  g_woh + wg + kt*32);
        CP_ASYNC16(base + 10240 + sow, g_wol + wg + kt*32);
        CP_COMMIT();
    };

    // ---- ldmatrix offsets ----
    int lrow = lane & 15, lc = lane >> 4;
    uint32_t a_off[2], w_off[2][2];
    #pragma unroll
    for (int kh = 0; kh < 2; kh++) {
        int row = wid*16 + lrow;
        a_off[kh] = (uint32_t)(row*64 + (((kh*2 + lc) ^ ((row>>1)&3))*16));
        #pragma unroll
        for (int h = 0; h < 2; h++) {
            int wr2 = h*16 + lrow;
            w_off[h][kh] = (uint32_t)(wr2*64 + (((kh*2 + lc) ^ ((wr2>>1)&3))*16));
        }
    }

    float acc[4][4];
    #pragma unroll
    for (int i = 0; i < 4; i++)
        #pragma unroll
        for (int q = 0; q < 4; q++) acc[i][q] = 0.f;

    load_stage(0, 0); load_stage(1, 1); load_stage(2, 2);

    for (int kt = 0; kt < OC_NIT; kt++) {
        if (kt + 2 < OC_NIT) asm volatile("cp.async.wait_group 2;" ::: "memory");
        else                 asm volatile("cp.async.wait_group 0;" ::: "memory");
        __syncthreads();
        if (kt + 3 < OC_NIT) load_stage((kt+3) & 3, kt+3);

        uint32_t base = sb + (uint32_t)(kt & 3) * OC_STG;
        #pragma unroll
        for (int kh = 0; kh < 2; kh++) {
            uint32_t ah[4], al[4];
            LDSM4(ah, base + a_off[kh]);
            LDSM4(al, base + 4096 + a_off[kh]);
            #pragma unroll
            for (int h = 0; h < 2; h++) {
                uint32_t wh[4], wl[4];
                LDSM4(wh, base + 8192 + w_off[h][kh]);
                LDSM4(wl, base + 10240 + w_off[h][kh]);
                MMA16816(acc[h*2],   ah, wh[0], wh[2]);
                MMA16816(acc[h*2+1], ah, wh[1], wh[3]);
                MMA16816(acc[h*2],   ah, wl[0], wl[2]);
                MMA16816(acc[h*2+1], ah, wl[1], wl[3]);
                MMA16816(acc[h*2],   al, wh[0], wh[2]);
                MMA16816(acc[h*2+1], al, wh[1], wh[3]);
            }
        }
    }

    int rr = bm + wid*16 + (lane >> 2);
    #pragma unroll
    for (int nj = 0; nj < 4; nj++) {
        int col = (nj >> 1)*16 + (nj & 1)*8 + (lane & 3)*2;
        float b0v = offb[col], b1v = offb[col+1];
        *(float2*)&g_off[(size_t)rr*NOFF + col] =
            make_float2(acc[nj][0] + b0v, acc[nj][1] + b1v);
        *(float2*)&g_off[(size_t)(rr+8)*NOFF + col] =
            make_float2(acc[nj][2] + b0v, acc[nj][3] + b1v);
    }
}

// =====================================================================
// Kernel 4: bilinear sampling -> plain fp16 A [m][k*96+c]
// warp per (m,k); lanes 0..23 each do 4 channels via float4
// =====================================================================
__global__ __launch_bounds__(256) void sample_kernel()
{
    int gw   = (blockIdx.x*256 + threadIdx.x) >> 5;
    int lane = threadIdx.x & 31;
    if (gw >= MM2*16) return;
    int m = gw >> 4, k = gw & 15;
    int b = m / SPA, s = m % SPA;
    int oh = s / HO, ow = s % HO;

    float offy = g_off[(size_t)m*NOFF + k*2];
    float offx = g_off[(size_t)m*NOFF + k*2 + 1];
    float py = (float)(oh*4 + (k >> 2)) + offy;
    float px = (float)(ow*4 + (k & 3)) + offx;
    float y0f = floorf(py), x0f = floorf(px);
    float wy = py - y0f, wx = px - x0f;
    int y0 = (int)y0f, x0 = (int)x0f;
    int y1 = y0 + 1,  x1 = x0 + 1;
    bool vy0 = (y0 >= 0) & (y0 < HH), vy1 = (y1 >= 0) & (y1 < HH);
    bool vx0 = (x0 >= 0) & (x0 < HH), vx1 = (x1 >= 0) & (x1 < HH);
    int cy0 = min(max(y0, 0), HH-1), cy1 = min(max(y1, 0), HH-1);
    int cx0 = min(max(x0, 0), HH-1), cx1 = min(max(x1, 0), HH-1);

    const float* hb = g_h + (size_t)b*HH*HH*CH;
    const float* p00 = hb + (size_t)(cy0*HH + cx0)*CH;
    const float* p01 = hb + (size_t)(cy0*HH + cx1)*CH;
    const float* p10 = hb + (size_t)(cy1*HH + cx0)*CH;
    const float* p11 = hb + (size_t)(cy1*HH + cx1)*CH;

    float w00 = (1.f-wy)*(1.f-wx) * (float)(vy0 && vx0);
    float w01 = (1.f-wy)*wx       * (float)(vy0 && vx1);
    float w10 = wy*(1.f-wx)       * (float)(vy1 && vx0);
    float w11 = wy*wx             * (float)(vy1 && vx1);

    if (lane < 24) {
        int c = lane*4;
        float4 a = *(const float4*)(p00 + c);
        float4 e = *(const float4*)(p01 + c);
        float4 f = *(const float4*)(p10 + c);
        float4 g = *(const float4*)(p11 + c);
        float vx0v = a.x*w00 + e.x*w01 + f.x*w10 + g.x*w11;
        float vy0v = a.y*w00 + e.y*w01 + f.y*w10 + g.y*w11;
        float vz0v = a.z*w00 + e.z*w01 + f.z*w10 + g.z*w11;
        float vw0v = a.w*w00 + e.w*w01 + f.w*w10 + g.w*w11;
        __half2* op = (__half2*)(g_Af + (size_t)m*KDIM + k*CH + c);
        op[0] = __floats2half2_rn(vx0v, vy0v);
        op[1] = __floats2half2_rn(vz0v, vw0v);
    }
}

// =====================================================================
// Kernel 5: 2-pass fp16 GEMM (A plain, B hi/lo) + BN2 + LeakyReLU
// CTA 128x256, BK=32, 8 warps (64x64), 4-stage cp.async
// =====================================================================
#define BK       32
#define NIT      48
#define OFF_BH   8192u
#define OFF_BL   24576u
#define STG_BYTES 40960u
#define NSTAGE   4
#define SMEM_GEMM (NSTAGE*STG_BYTES + 2048)

__global__ __launch_bounds__(256, 1) void gemm_mma_kernel(
    const float* __restrict__ dcnb, const float* __restrict__ g2,
    const float* __restrict__ b2,   const float* __restrict__ bn2m,
    const float* __restrict__ v2,   float* __restrict__ out)
{
    extern __shared__ char smem[];
    uint32_t sb = smem_to_u32(smem);
    float* sScale = (float*)(smem + NSTAGE*STG_BYTES);
    float* sBeta  = sScale + 256;

    int tid  = threadIdx.x;
    int lane = tid & 31, wid = tid >> 5;
    int wm = wid & 1, wn = wid >> 1;
    int bm = blockIdx.y * 128;
    int bn = blockIdx.x * 256;

    {
        int n = bn + tid;
        float inv = g2[n] * rsqrtf(v2[n] + 1e-5f);
        sScale[tid] = inv;
        sBeta[tid]  = (dcnb[n] - bn2m[n])*inv + b2[n];
    }

    auto load_stage = [&](int stg, int kt) {
        uint32_t base = sb + (uint32_t)stg * STG_BYTES;
        int ks = kt * BK;
        #pragma unroll
        for (int i = 0; i < 2; i++) {             // A: 512 chunks
            int id = tid + i*256;
            int row = id >> 2, c = id & 3;
            uint32_t so = (uint32_t)(row*64 + ((c ^ ((row>>1)&3))*16));
            CP_ASYNC16(base + so, g_Af + (size_t)(bm+row)*KDIM + ks + c*8);
        }
        #pragma unroll
        for (int i = 0; i < 4; i++) {             // B hi+lo: 1024 chunks each
            int id = tid + i*256;
            int row = id >> 2, c = id & 3;
            uint32_t so = (uint32_t)(row*64 + ((c ^ ((row>>1)&3))*16));
            size_t gi = (size_t)(bn+row)*KDIM + ks + c*8;
            CP_ASYNC16(base + OFF_BH + so, g_Bhi + gi);
            CP_ASYNC16(base + OFF_BL + so, g_Blo + gi);
        }
        CP_COMMIT();
    };

    int lrow = lane & 15, lc = lane >> 4;
    uint32_t a_off[4][2], b_off[4][2];
    #pragma unroll
    for (int mi = 0; mi < 4; mi++) {
        int row = wm*64 + mi*16 + lrow;
        int rs = (row >> 1) & 3;
        #pragma unroll
        for (int kh = 0; kh < 2; kh++)
            a_off[mi][kh] = (uint32_t)(row*64 + (((kh*2 + lc) ^ rs) * 16));
    }
    #pragma unroll
    for (int nb = 0; nb < 4; nb++) {
        int row = wn*64 + nb*16 + lrow;
        int rs = (row >> 1) & 3;
        #pragma unroll
        for (int kh = 0; kh < 2; kh++)
            b_off[nb][kh] = (uint32_t)(row*64 + (((kh*2 + lc) ^ rs) * 16));
    }

    float acc[4][8][4];
    #pragma unroll
    for (int i = 0; i < 4; i++)
        #pragma unroll
        for (int j = 0; j < 8; j++)
            #pragma unroll
            for (int q = 0; q < 4; q++) acc[i][j][q] = 0.f;

    load_stage(0, 0); load_stage(1, 1); load_stage(2, 2);

    for (int kt = 0; kt < NIT; kt++) {
        if (kt + 2 < NIT) asm volatile("cp.async.wait_group 2;" ::: "memory");
        else              asm volatile("cp.async.wait_group 0;" ::: "memory");
        __syncthreads();
        if (kt + 3 < NIT) load_stage((kt+3) & 3, kt+3);

        uint32_t base = sb + (uint32_t)(kt & 3) * STG_BYTES;
        #pragma unroll
        for (int kh = 0; kh < 2; kh++) {
            uint32_t a[4][4];
            #pragma unroll
            for (int mi = 0; mi < 4; mi++)
                LDSM4(a[mi], base + a_off[mi][kh]);
            #pragma unroll
            for (int nb = 0; nb < 4; nb++) {
                uint32_t bh[4], bl[4];
                LDSM4(bh, base + OFF_BH + b_off[nb][kh]);
                LDSM4(bl, base + OFF_BL + b_off[nb][kh]);
                #pragma unroll
                for (int mi = 0; mi < 4; mi++) {
                    MMA16816(acc[mi][2*nb],   a[mi], bh[0], bh[2]);
                    MMA16816(acc[mi][2*nb+1], a[mi], bh[1], bh[3]);
                    MMA16816(acc[mi][2*nb],   a[mi], bl[0], bl[2]);
                    MMA16816(acc[mi][2*nb+1], a[mi], bl[1], bl[3]);
                }
            }
        }
    }

    // ---- epilogue: BN2 + LeakyReLU, final (B, HoWo, C) layout ----
    #pragma unroll
    for (int mi = 0; mi < 4; mi++) {
        int r0 = bm + wm*64 + mi*16 + (lane >> 2);
        #pragma unroll
        for (int nj = 0; nj < 8; nj++) {
            int colL = wn*64 + nj*8 + (lane & 3)*2;
            float s0 = sScale[colL],   s1 = sScale[colL+1];
            float e0 = sBeta[colL],    e1 = sBeta[colL+1];
            float v0 = acc[mi][nj][0]*s0 + e0;
            float v1 = acc[mi][nj][1]*s1 + e1;
            float v2 = acc[mi][nj][2]*s0 + e0;
            float v3 = acc[mi][nj][3]*s1 + e1;
            v0 = (v0 >= 0.f) ? v0 : 0.01f*v0;
            v1 = (v1 >= 0.f) ? v1 : 0.01f*v1;
            v2 = (v2 >= 0.f) ? v2 : 0.01f*v2;
            v3 = (v3 >= 0.f) ? v3 : 0.01f*v3;
            *(float2*)&out[(size_t)r0*ND + bn + colL]     = make_float2(v0, v1);
            *(float2*)&out[(size_t)(r0+8)*ND + bn + colL] = make_float2(v2, v3);
        }
    }
}

// =====================================================================
extern "C" void kernel_launch(void* const* d_in, const int* in_sizes, int n_in,
                              void* d_out, int out_size)
{
    const float* x      = (const float*)d_in[0];
    const float* stem_w = (const float*)d_in[1];
    const float* stem_b = (const float*)d_in[2];
    const float* bn1_g  = (const float*)d_in[3];
    const float* bn1_b  = (const float*)d_in[4];
    const float* bn1_m  = (const float*)d_in[5];
    const float* bn1_v  = (const float*)d_in[6];
    const float* off_w  = (const float*)d_in[7];
    const float* off_b  = (const float*)d_in[8];
    const float* dcn_w  = (const float*)d_in[9];
    const float* dcn_b  = (const float*)d_in[10];
    const float* bn2_g  = (const float*)d_in[11];
    const float* bn2_b  = (const float*)d_in[12];
    const float* bn2_m  = (const float*)d_in[13];
    const float* bn2_v  = (const float*)d_in[14];
    float* out = (float*)d_out;

    cudaFuncSetAttribute(gemm_mma_kernel,
                         cudaFuncAttributeMaxDynamicSharedMemorySize, SMEM_GEMM);
    cudaFuncSetAttribute(offconv_mma_kernel,
                         cudaFuncAttributeMaxDynamicSharedMemorySize, SMEM_OC);

    stem_kernel<<<NB*HH, 192>>>(x, stem_w, stem_b, bn1_g, bn1_b, bn1_m, bn1_v);
    prep_kernel<<<(ND*KDIM + 255)/256, 256>>>(dcn_w, off_w);
    offconv_mma_kernel<<<MM2/64, 128, SMEM_OC>>>(off_b);
    sample_kernel<<<(MM2*16*32)/256, 256>>>();
    gemm_mma_kernel<<<dim3(ND/256, MM2/128), 256, SMEM_GEMM>>>(
        dcn_b, bn2_g, bn2_b, bn2_m, bn2_v, out);
}

// round 5
// speedup vs baseline: 3.1319x; 1.3261x over previous
#include <cuda_runtime.h>
#include <cuda_fp16.h>
#include <cstdint>

// ---------------- problem constants ----------------
#define NB    64
#define CIN   3
#define HIN   224
#define CH    96
#define HH    56
#define HO    14
#define SPA   196
#define MM2   12544   // GEMM M
#define KDIM  1536    // GEMM K
#define ND    768     // GEMM N
#define NOFF  32

// ---------------- scratch (device globals) ----------------
__device__ __half g_hh[(size_t)NB*HH*HH*CH];   // stem output fp16 hi
__device__ __half g_hl[(size_t)NB*HH*HH*CH];   // stem output fp16 lo (offconv)
__device__ float  g_off[(size_t)MM2*NOFF];     // offsets [m][32]
__device__ __half g_woh[(size_t)NOFF*KDIM];    // off_w [n][k*96+c] fp16 hi
__device__ __half g_wol[(size_t)NOFF*KDIM];    // off_w fp16 lo
__device__ __half g_Af [(size_t)MM2*KDIM];     // sampled A, plain fp16
__device__ __half g_Bhi[(size_t)ND*KDIM];      // dcn_w [o][k*96+c] fp16

// ==================== PTX helpers (plain-target safe) ====================
__device__ __forceinline__ uint32_t smem_to_u32(const void* p) {
    uint32_t a;
    asm("{ .reg .u64 t; cvta.to.shared.u64 t, %1; cvt.u32.u64 %0, t; }" : "=r"(a) : "l"(p));
    return a;
}
#define CP_ASYNC16(s, g) \
    asm volatile("cp.async.cg.shared.global [%0], [%1], 16;" :: "r"(s), "l"(g) : "memory")
#define CP_COMMIT() asm volatile("cp.async.commit_group;" ::: "memory")
#define LDSM4(r, a) \
    asm volatile("ldmatrix.sync.aligned.m8n8.x4.shared.b16 {%0,%1,%2,%3}, [%4];" \
        : "=r"((r)[0]), "=r"((r)[1]), "=r"((r)[2]), "=r"((r)[3]) : "r"(a))
#define MMA16816(d, a, b0v, b1v) \
    asm volatile("mma.sync.aligned.m16n8k16.row.col.f32.f16.f16.f32 " \
        "{%0,%1,%2,%3},{%4,%5,%6,%7},{%8,%9},{%0,%1,%2,%3};" \
        : "+f"((d)[0]), "+f"((d)[1]), "+f"((d)[2]), "+f"((d)[3]) \
        : "r"((a)[0]), "r"((a)[1]), "r"((a)[2]), "r"((a)[3]), "r"(b0v), "r"(b1v))

// =====================================================================
// Kernel 1: stem conv + BN1 + LeakyReLU -> g_hh/g_hl (fp16 hi/lo)
// =====================================================================
__global__ __launch_bounds__(192) void stem_kernel(
    const float* __restrict__ x, const float* __restrict__ w,
    const float* __restrict__ bias,
    const float* __restrict__ g1, const float* __restrict__ b1,
    const float* __restrict__ m1, const float* __restrict__ v1)
{
    int b  = blockIdx.x / HH;
    int oh = blockIdx.x % HH;
    __shared__ float sx[CIN*4*HIN];
    __shared__ float sinv[CH], sbeta[CH];
    int tid = threadIdx.x;

    for (int i = tid; i < CIN*4*HIN; i += 192) {
        int j = i / HIN, col = i % HIN;
        int c = j >> 2, kh = j & 3;
        sx[i] = x[((size_t)(b*CIN + c)*HIN + (4*oh + kh))*HIN + col];
    }
    if (tid < CH) {
        float inv = g1[tid] * rsqrtf(v1[tid] + 1e-5f);
        sinv[tid]  = inv;
        sbeta[tid] = (bias[tid] - m1[tid]) * inv + b1[tid];
    }
    __syncthreads();

    int o = tid % CH, owb = tid / CH;
    float4 wr[12];
    #pragma unroll
    for (int j = 0; j < 12; j++) wr[j] = *(const float4*)&w[o*48 + j*4];
    float inv = sinv[o], beta = sbeta[o];

    for (int ow = owb; ow < HH; ow += 2) {
        float acc = 0.f;
        #pragma unroll
        for (int j = 0; j < 12; j++) {
            float4 xv = *(const float4*)&sx[j*HIN + 4*ow];
            acc += xv.x*wr[j].x + xv.y*wr[j].y + xv.z*wr[j].z + xv.w*wr[j].w;
        }
        float val = acc*inv + beta;
        val = (val >= 0.f) ? val : 0.01f*val;
        size_t idx = ((size_t)(b*HH + oh)*HH + ow)*CH + o;
        __half hv = __float2half(val);
        g_hh[idx] = hv;
        g_hl[idx] = __float2half(val - __half2float(hv));
    }
}

// =====================================================================
// Kernel 2: weight prep (dcn_w fp16, off_w fp16 hi/lo, both [n][k*96+c])
// =====================================================================
__global__ __launch_bounds__(256) void prep_kernel(
    const float* __restrict__ wd, const float* __restrict__ wo)
{
    int i = blockIdx.x*256 + threadIdx.x;
    if (i < ND*KDIM) {
        int o = i / KDIM, r = i % KDIM;
        int k = r / CH, c = r % CH;
        g_Bhi[i] = __float2half(wd[(size_t)o*KDIM + c*16 + k]);
    }
    if (i < NOFF*KDIM) {
        int n = i / KDIM, r = i % KDIM;
        int k = r / CH, c = r % CH;
        float v = wo[(size_t)n*KDIM + c*16 + k];
        __half hi = __float2half(v);
        g_woh[i] = hi;
        g_wol[i] = __float2half(v - __half2float(hi));
    }
}

// =====================================================================
// Kernel 3: offset conv via mma.sync, 3-pass fp16 hi/lo (exact offsets)
// M-tile 64, N=32, BK=32, 4 warps, 4-stage cp.async, im2col on the fly
// =====================================================================
#define OC_NIT 48
#define OC_STG 12288u    // Ah 4K | Al 4K | Wh 2K | Wl 2K
#define SMEM_OC (4*OC_STG)

__global__ __launch_bounds__(128, 1) void offconv_mma_kernel(const float* __restrict__ offb)
{
    extern __shared__ char smem[];
    uint32_t sb = smem_to_u32(smem);
    int tid = threadIdx.x;
    int lane = tid & 31, wid = tid >> 5;
    int bm = blockIdx.x * 64;

    int c4 = tid & 3;
    int r0 = tid >> 2, r1 = r0 + 32;
    int m0 = bm + r0, m1v = bm + r1;
    int b0 = m0 / SPA, s0 = m0 % SPA;
    int b1 = m1v / SPA, s1 = m1v % SPA;
    size_t rb0 = ((size_t)(b0*HH + (s0/HO)*4)*HH + (s0%HO)*4)*CH;
    size_t rb1 = ((size_t)(b1*HH + (s1/HO)*4)*HH + (s1%HO)*4)*CH;
    uint32_t so0 = (uint32_t)(r0*64 + ((c4 ^ ((r0>>1)&3))*16));
    uint32_t so1 = (uint32_t)(r1*64 + ((c4 ^ ((r1>>1)&3))*16));
    int wrow = tid >> 2;
    uint32_t sow = (uint32_t)(wrow*64 + ((c4 ^ ((wrow>>1)&3))*16));
    size_t wg = (size_t)wrow*KDIM + c4*8;

    auto load_stage = [&](int stg, int kt) {
        uint32_t base = sb + (uint32_t)stg * OC_STG;
        int kpix = kt / 3;
        int poff = (kpix >> 2)*(HH*CH) + (kpix & 3)*CH + (kt - kpix*3)*32 + c4*8;
        CP_ASYNC16(base + so0,         g_hh + rb0 + poff);
        CP_ASYNC16(base + 4096 + so0,  g_hl + rb0 + poff);
        CP_ASYNC16(base + so1,         g_hh + rb1 + poff);
        CP_ASYNC16(base + 4096 + so1,  g_hl + rb1 + poff);
        CP_ASYNC16(base + 8192 + sow,  g_woh + wg + kt*32);
        CP_ASYNC16(base + 10240 + sow, g_wol + wg + kt*32);
        CP_COMMIT();
    };

    int lrow = lane & 15, lc = lane >> 4;
    uint32_t a_off[2], w_off[2][2];
    #pragma unroll
    for (int kh = 0; kh < 2; kh++) {
        int row = wid*16 + lrow;
        a_off[kh] = (uint32_t)(row*64 + (((kh*2 + lc) ^ ((row>>1)&3))*16));
        #pragma unroll
        for (int h = 0; h < 2; h++) {
            int wr2 = h*16 + lrow;
            w_off[h][kh] = (uint32_t)(wr2*64 + (((kh*2 + lc) ^ ((wr2>>1)&3))*16));
        }
    }

    float acc[4][4];
    #pragma unroll
    for (int i = 0; i < 4; i++)
        #pragma unroll
        for (int q = 0; q < 4; q++) acc[i][q] = 0.f;

    load_stage(0, 0); load_stage(1, 1); load_stage(2, 2);

    for (int kt = 0; kt < OC_NIT; kt++) {
        if (kt + 2 < OC_NIT) asm volatile("cp.async.wait_group 2;" ::: "memory");
        else                 asm volatile("cp.async.wait_group 0;" ::: "memory");
        __syncthreads();
        if (kt + 3 < OC_NIT) load_stage((kt+3) & 3, kt+3);

        uint32_t base = sb + (uint32_t)(kt & 3) * OC_STG;
        #pragma unroll
        for (int kh = 0; kh < 2; kh++) {
            uint32_t ah[4], al[4];
            LDSM4(ah, base + a_off[kh]);
            LDSM4(al, base + 4096 + a_off[kh]);
            #pragma unroll
            for (int h = 0; h < 2; h++) {
                uint32_t wh[4], wl[4];
                LDSM4(wh, base + 8192 + w_off[h][kh]);
                LDSM4(wl, base + 10240 + w_off[h][kh]);
                MMA16816(acc[h*2],   ah, wh[0], wh[2]);
                MMA16816(acc[h*2+1], ah, wh[1], wh[3]);
                MMA16816(acc[h*2],   ah, wl[0], wl[2]);
                MMA16816(acc[h*2+1], ah, wl[1], wl[3]);
                MMA16816(acc[h*2],   al, wh[0], wh[2]);
                MMA16816(acc[h*2+1], al, wh[1], wh[3]);
            }
        }
    }

    int rr = bm + wid*16 + (lane >> 2);
    #pragma unroll
    for (int nj = 0; nj < 4; nj++) {
        int col = (nj >> 1)*16 + (nj & 1)*8 + (lane & 3)*2;
        float b0v = offb[col], b1v = offb[col+1];
        *(float2*)&g_off[(size_t)rr*NOFF + col] =
            make_float2(acc[nj][0] + b0v, acc[nj][1] + b1v);
        *(float2*)&g_off[(size_t)(rr+8)*NOFF + col] =
            make_float2(acc[nj][2] + b0v, acc[nj][3] + b1v);
    }
}

// =====================================================================
// Kernel 4: bilinear sampling (fp16 source) -> fp16 A [m][k*96+c]
// One warp per m. Lanes 0-15 precompute 16 k-prologues; then 16 dense
// iterations with shfl broadcast, lanes 0-23 x 4 channels (uint2 loads).
// =====================================================================
__global__ __launch_bounds__(256) void sample_kernel()
{
    int m    = (blockIdx.x*256 + threadIdx.x) >> 5;
    int lane = threadIdx.x & 31;
    int b = m / SPA, s = m % SPA;
    int oh = s / HO, ow = s % HO;

    int e00 = 0, e01 = 0, e10 = 0, e11 = 0;
    float w00 = 0.f, w01 = 0.f, w10 = 0.f, w11 = 0.f;
    if (lane < 16) {
        int k = lane;
        float offy = g_off[(size_t)m*NOFF + k*2];
        float offx = g_off[(size_t)m*NOFF + k*2 + 1];
        float py = (float)(oh*4 + (k >> 2)) + offy;
        float px = (float)(ow*4 + (k & 3)) + offx;
        float y0f = floorf(py), x0f = floorf(px);
        float wy = py - y0f, wx = px - x0f;
        int y0 = (int)y0f, x0 = (int)x0f;
        int y1 = y0 + 1,  x1 = x0 + 1;
        bool vy0 = (y0 >= 0) & (y0 < HH), vy1 = (y1 >= 0) & (y1 < HH);
        bool vx0 = (x0 >= 0) & (x0 < HH), vx1 = (x1 >= 0) & (x1 < HH);
        int cy0 = min(max(y0, 0), HH-1), cy1 = min(max(y1, 0), HH-1);
        int cx0 = min(max(x0, 0), HH-1), cx1 = min(max(x1, 0), HH-1);
        e00 = (cy0*HH + cx0)*CH;
        e01 = (cy0*HH + cx1)*CH;
        e10 = (cy1*HH + cx0)*CH;
        e11 = (cy1*HH + cx1)*CH;
        w00 = (1.f-wy)*(1.f-wx) * (float)(vy0 && vx0);
        w01 = (1.f-wy)*wx       * (float)(vy0 && vx1);
        w10 = wy*(1.f-wx)       * (float)(vy1 && vx0);
        w11 = wy*wx             * (float)(vy1 && vx1);
    }

    const __half* hb = g_hh + (size_t)b*HH*HH*CH;
    __half* ob = g_Af + (size_t)m*KDIM;
    int c = (lane < 24) ? lane*4 : 0;

    #pragma unroll 4
    for (int k = 0; k < 16; k++) {
        int   f00 = __shfl_sync(0xFFFFFFFFu, e00, k);
        int   f01 = __shfl_sync(0xFFFFFFFFu, e01, k);
        int   f10 = __shfl_sync(0xFFFFFFFFu, e10, k);
        int   f11 = __shfl_sync(0xFFFFFFFFu, e11, k);
        float q00 = __shfl_sync(0xFFFFFFFFu, w00, k);
        float q01 = __shfl_sync(0xFFFFFFFFu, w01, k);
        float q10 = __shfl_sync(0xFFFFFFFFu, w10, k);
        float q11 = __shfl_sync(0xFFFFFFFFu, w11, k);
        if (lane < 24) {
            uint2 u00 = *(const uint2*)(hb + f00 + c);
            uint2 u01 = *(const uint2*)(hb + f01 + c);
            uint2 u10 = *(const uint2*)(hb + f10 + c);
            uint2 u11 = *(const uint2*)(hb + f11 + c);
            float2 a0 = __half22float2(*(__half2*)&u00.x);
            float2 a1 = __half22float2(*(__half2*)&u00.y);
            float2 b0 = __half22float2(*(__half2*)&u01.x);
            float2 b1 = __half22float2(*(__half2*)&u01.y);
            float2 c0 = __half22float2(*(__half2*)&u10.x);
            float2 c1 = __half22float2(*(__half2*)&u10.y);
            float2 d0 = __half22float2(*(__half2*)&u11.x);
            float2 d1 = __half22float2(*(__half2*)&u11.y);
            float r0 = a0.x*q00 + b0.x*q01 + c0.x*q10 + d0.x*q11;
            float r1 = a0.y*q00 + b0.y*q01 + c0.y*q10 + d0.y*q11;
            float r2 = a1.x*q00 + b1.x*q01 + c1.x*q10 + d1.x*q11;
            float r3 = a1.y*q00 + b1.y*q01 + c1.y*q10 + d1.y*q11;
            __half2 h0 = __floats2half2_rn(r0, r1);
            __half2 h1 = __floats2half2_rn(r2, r3);
            uint2 o;
            o.x = *(uint32_t*)&h0;
            o.y = *(uint32_t*)&h1;
            *(uint2*)(ob + k*CH + c) = o;
        }
    }
}

// =====================================================================
// Kernel 5: single-pass fp16 GEMM + BN2 + LeakyReLU
// CTA 128x256, BK=32, 8 warps (64x64), 4-stage cp.async
// =====================================================================
#define BK       32
#define NIT      48
#define OFF_B    8192u
#define STG_BYTES 24576u
#define NSTAGE   4
#define SMEM_GEMM (NSTAGE*STG_BYTES + 2048)

__global__ __launch_bounds__(256, 1) void gemm_mma_kernel(
    const float* __restrict__ dcnb, const float* __restrict__ g2,
    const float* __restrict__ b2,   const float* __restrict__ bn2m,
    const float* __restrict__ v2,   float* __restrict__ out)
{
    extern __shared__ char smem[];
    uint32_t sb = smem_to_u32(smem);
    float* sScale = (float*)(smem + NSTAGE*STG_BYTES);
    float* sBeta  = sScale + 256;

    int tid  = threadIdx.x;
    int lane = tid & 31, wid = tid >> 5;
    int wm = wid & 1, wn = wid >> 1;
    int bm = blockIdx.y * 128;
    int bn = blockIdx.x * 256;

    {
        int n = bn + tid;
        float inv = g2[n] * rsqrtf(v2[n] + 1e-5f);
        sScale[tid] = inv;
        sBeta[tid]  = (dcnb[n] - bn2m[n])*inv + b2[n];
    }

    auto load_stage = [&](int stg, int kt) {
        uint32_t base = sb + (uint32_t)stg * STG_BYTES;
        int ks = kt * BK;
        #pragma unroll
        for (int i = 0; i < 2; i++) {             // A: 512 chunks
            int id = tid + i*256;
            int row = id >> 2, c = id & 3;
            uint32_t so = (uint32_t)(row*64 + ((c ^ ((row>>1)&3))*16));
            CP_ASYNC16(base + so, g_Af + (size_t)(bm+row)*KDIM + ks + c*8);
        }
        #pragma unroll
        for (int i = 0; i < 4; i++) {             // B: 1024 chunks
            int id = tid + i*256;
            int row = id >> 2, c = id & 3;
            uint32_t so = (uint32_t)(row*64 + ((c ^ ((row>>1)&3))*16));
            CP_ASYNC16(base + OFF_B + so, g_Bhi + (size_t)(bn+row)*KDIM + ks + c*8);
        }
        CP_COMMIT();
    };

    int lrow = lane & 15, lc = lane >> 4;
    uint32_t a_off[4][2], b_off[4][2];
    #pragma unroll
    for (int mi = 0; mi < 4; mi++) {
        int row = wm*64 + mi*16 + lrow;
        int rs = (row >> 1) & 3;
        #pragma unroll
        for (int kh = 0; kh < 2; kh++)
            a_off[mi][kh] = (uint32_t)(row*64 + (((kh*2 + lc) ^ rs) * 16));
    }
    #pragma unroll
    for (int nb = 0; nb < 4; nb++) {
        int row = wn*64 + nb*16 + lrow;
        int rs = (row >> 1) & 3;
        #pragma unroll
        for (int kh = 0; kh < 2; kh++)
            b_off[nb][kh] = (uint32_t)(row*64 + (((kh*2 + lc) ^ rs) * 16));
    }

    float acc[4][8][4];
    #pragma unroll
    for (int i = 0; i < 4; i++)
        #pragma unroll
        for (int j = 0; j < 8; j++)
            #pragma unroll
            for (int q = 0; q < 4; q++) acc[i][j][q] = 0.f;

    load_stage(0, 0); load_stage(1, 1); load_stage(2, 2);

    for (int kt = 0; kt < NIT; kt++) {
        if (kt + 2 < NIT) asm volatile("cp.async.wait_group 2;" ::: "memory");
        else              asm volatile("cp.async.wait_group 0;" ::: "memory");
        __syncthreads();
        if (kt + 3 < NIT) load_stage((kt+3) & 3, kt+3);

        uint32_t base = sb + (uint32_t)(kt & 3) * STG_BYTES;
        #pragma unroll
        for (int kh = 0; kh < 2; kh++) {
            uint32_t a[4][4];
            #pragma unroll
            for (int mi = 0; mi < 4; mi++)
                LDSM4(a[mi], base + a_off[mi][kh]);
            #pragma unroll
            for (int nb = 0; nb < 4; nb++) {
                uint32_t bh[4];
                LDSM4(bh, base + OFF_B + b_off[nb][kh]);
                #pragma unroll
                for (int mi = 0; mi < 4; mi++) {
                    MMA16816(acc[mi][2*nb],   a[mi], bh[0], bh[2]);
                    MMA16816(acc[mi][2*nb+1], a[mi], bh[1], bh[3]);
                }
            }
        }
    }

    // ---- epilogue: BN2 + LeakyReLU, final (B, HoWo, C) layout ----
    #pragma unroll
    for (int mi = 0; mi < 4; mi++) {
        int r0 = bm + wm*64 + mi*16 + (lane >> 2);
        #pragma unroll
        for (int nj = 0; nj < 8; nj++) {
            int colL = wn*64 + nj*8 + (lane & 3)*2;
            float s0 = sScale[colL],   s1 = sScale[colL+1];
            float e0 = sBeta[colL],    e1 = sBeta[colL+1];
            float v0 = acc[mi][nj][0]*s0 + e0;
            float v1 = acc[mi][nj][1]*s1 + e1;
            float v2 = acc[mi][nj][2]*s0 + e0;
            float v3 = acc[mi][nj][3]*s1 + e1;
            v0 = (v0 >= 0.f) ? v0 : 0.01f*v0;
            v1 = (v1 >= 0.f) ? v1 : 0.01f*v1;
            v2 = (v2 >= 0.f) ? v2 : 0.01f*v2;
            v3 = (v3 >= 0.f) ? v3 : 0.01f*v3;
            *(float2*)&out[(size_t)r0*ND + bn + colL]     = make_float2(v0, v1);
            *(float2*)&out[(size_t)(r0+8)*ND + bn + colL] = make_float2(v2, v3);
        }
    }
}

// =====================================================================
extern "C" void kernel_launch(void* const* d_in, const int* in_sizes, int n_in,
                              void* d_out, int out_size)
{
    const float* x      = (const float*)d_in[0];
    const float* stem_w = (const float*)d_in[1];
    const float* stem_b = (const float*)d_in[2];
    const float* bn1_g  = (const float*)d_in[3];
    const float* bn1_b  = (const float*)d_in[4];
    const float* bn1_m  = (const float*)d_in[5];
    const float* bn1_v  = (const float*)d_in[6];
    const float* off_w  = (const float*)d_in[7];
    const float* off_b  = (const float*)d_in[8];
    const float* dcn_w  = (const float*)d_in[9];
    const float* dcn_b  = (const float*)d_in[10];
    const float* bn2_g  = (const float*)d_in[11];
    const float* bn2_b  = (const float*)d_in[12];
    const float* bn2_m  = (const float*)d_in[13];
    const float* bn2_v  = (const float*)d_in[14];
    float* out = (float*)d_out;

    cudaFuncSetAttribute(gemm_mma_kernel,
                         cudaFuncAttributeMaxDynamicSharedMemorySize, SMEM_GEMM);
    cudaFuncSetAttribute(offconv_mma_kernel,
                         cudaFuncAttributeMaxDynamicSharedMemorySize, SMEM_OC);

    stem_kernel<<<NB*HH, 192>>>(x, stem_w, stem_b, bn1_g, bn1_b, bn1_m, bn1_v);
    prep_kernel<<<(ND*KDIM + 255)/256, 256>>>(dcn_w, off_w);
    offconv_mma_kernel<<<MM2/64, 128, SMEM_OC>>>(off_b);
    sample_kernel<<<MM2*32/256, 256>>>();
    gemm_mma_kernel<<<dim3(ND/256, MM2/128), 256, SMEM_GEMM>>>(
        dcn_b, bn2_g, bn2_b, bn2_m, bn2_v, out);
}

// round 7
// speedup vs baseline: 3.3706x; 1.0762x over previous
#include <cuda_runtime.h>
#include <cuda_fp16.h>
#include <cstdint>

// ---------------- problem constants ----------------
#define NB    64
#define CIN   3
#define HIN   224
#define CH    96
#define HH    56
#define HO    14
#define SPA   196
#define MM2   12544   // GEMM M
#define KDIM  1536    // GEMM K
#define ND    768     // GEMM N
#define NOFF  32

// ---------------- scratch (device globals) ----------------
__device__ __half g_hh[(size_t)NB*HH*HH*CH];   // stem output fp16 NHWC
__device__ float  g_off[(size_t)MM2*NOFF];     // offsets [m][32]
__device__ __half g_woh[(size_t)NOFF*KDIM];    // off_w [n][k*96+c] fp16
__device__ __half g_Af [(size_t)MM2*KDIM];     // sampled A, fp16
__device__ __half g_Bhi[(size_t)ND*KDIM];      // dcn_w [o][k*96+c] fp16

// ==================== PTX helpers (plain-target safe) ====================
__device__ __forceinline__ uint32_t smem_to_u32(const void* p) {
    uint32_t a;
    asm("{ .reg .u64 t; cvta.to.shared.u64 t, %1; cvt.u32.u64 %0, t; }" : "=r"(a) : "l"(p));
    return a;
}
#define CP_ASYNC16(s, g) \
    asm volatile("cp.async.cg.shared.global [%0], [%1], 16;" :: "r"(s), "l"(g) : "memory")
#define CP_COMMIT() asm volatile("cp.async.commit_group;" ::: "memory")
#define LDSM4(r, a) \
    asm volatile("ldmatrix.sync.aligned.m8n8.x4.shared.b16 {%0,%1,%2,%3}, [%4];" \
        : "=r"((r)[0]), "=r"((r)[1]), "=r"((r)[2]), "=r"((r)[3]) : "r"(a))
#define MMA16816(d, a, b0v, b1v) \
    asm volatile("mma.sync.aligned.m16n8k16.row.col.f32.f16.f16.f32 " \
        "{%0,%1,%2,%3},{%4,%5,%6,%7},{%8,%9},{%0,%1,%2,%3};" \
        : "+f"((d)[0]), "+f"((d)[1]), "+f"((d)[2]), "+f"((d)[3]) \
        : "r"((a)[0]), "r"((a)[1]), "r"((a)[2]), "r"((a)[3]), "r"(b0v), "r"(b1v))

// =====================================================================
// Kernel 1: stem conv + BN1 + LeakyReLU -> g_hh (fp16 NHWC)
// =====================================================================
__global__ __launch_bounds__(192) void stem_kernel(
    const float* __restrict__ x, const float* __restrict__ w,
    const float* __restrict__ bias,
    const float* __restrict__ g1, const float* __restrict__ b1,
    const float* __restrict__ m1, const float* __restrict__ v1)
{
    int b  = blockIdx.x / HH;
    int oh = blockIdx.x % HH;
    __shared__ float sx[CIN*4*HIN];
    __shared__ float sinv[CH], sbeta[CH];
    int tid = threadIdx.x;

    for (int i = tid; i < CIN*4*HIN; i += 192) {
        int j = i / HIN, col = i % HIN;
        int c = j >> 2, kh = j & 3;
        sx[i] = x[((size_t)(b*CIN + c)*HIN + (4*oh + kh))*HIN + col];
    }
    if (tid < CH) {
        float inv = g1[tid] * rsqrtf(v1[tid] + 1e-5f);
        sinv[tid]  = inv;
        sbeta[tid] = (bias[tid] - m1[tid]) * inv + b1[tid];
    }
    __syncthreads();

    int o = tid % CH, owb = tid / CH;
    float4 wr[12];
    #pragma unroll
    for (int j = 0; j < 12; j++) wr[j] = *(const float4*)&w[o*48 + j*4];
    float inv = sinv[o], beta = sbeta[o];

    for (int ow = owb; ow < HH; ow += 2) {
        float acc = 0.f;
        #pragma unroll
        for (int j = 0; j < 12; j++) {
            float4 xv = *(const float4*)&sx[j*HIN + 4*ow];
            acc += xv.x*wr[j].x + xv.y*wr[j].y + xv.z*wr[j].z + xv.w*wr[j].w;
        }
        float val = acc*inv + beta;
        val = (val >= 0.f) ? val : 0.01f*val;
        g_hh[((size_t)(b*HH + oh)*HH + ow)*CH + o] = __float2half(val);
    }
}

// =====================================================================
// Kernel 2: weight prep (dcn_w fp16, off_w fp16, both [n][k*96+c])
// =====================================================================
__global__ __launch_bounds__(256) void prep_kernel(
    const float* __restrict__ wd, const float* __restrict__ wo)
{
    int i = blockIdx.x*256 + threadIdx.x;
    if (i < ND*KDIM) {
        int o = i / KDIM, r = i % KDIM;
        int k = r / CH, c = r % CH;
        g_Bhi[i] = __float2half(wd[(size_t)o*KDIM + c*16 + k]);
    }
    if (i < NOFF*KDIM) {
        int n = i / KDIM, r = i % KDIM;
        int k = r / CH, c = r % CH;
        g_woh[i] = __float2half(wo[(size_t)n*KDIM + c*16 + k]);
    }
}

// =====================================================================
// Kernel 3: offset conv via mma.sync, single-pass fp16
// M-tile 64, N=32, BK=32, 4 warps, 4-stage cp.async, im2col on the fly
// =====================================================================
#define OC_NIT 48
#define OC_STG 6144u     // Ah 4K | Wh 2K
#define SMEM_OC (4*OC_STG)

__global__ __launch_bounds__(128, 1) void offconv_mma_kernel(const float* __restrict__ offb)
{
    extern __shared__ char smem[];
    uint32_t sb = smem_to_u32(smem);
    int tid = threadIdx.x;
    int lane = tid & 31, wid = tid >> 5;
    int bm = blockIdx.x * 64;

    int c4 = tid & 3;
    int r0 = tid >> 2, r1 = r0 + 32;
    int m0 = bm + r0, m1v = bm + r1;
    int b0 = m0 / SPA, s0 = m0 % SPA;
    int b1 = m1v / SPA, s1 = m1v % SPA;
    size_t rb0 = ((size_t)(b0*HH + (s0/HO)*4)*HH + (s0%HO)*4)*CH;
    size_t rb1 = ((size_t)(b1*HH + (s1/HO)*4)*HH + (s1%HO)*4)*CH;
    uint32_t so0 = (uint32_t)(r0*64 + ((c4 ^ ((r0>>1)&3))*16));
    uint32_t so1 = (uint32_t)(r1*64 + ((c4 ^ ((r1>>1)&3))*16));
    int wrow = tid >> 2;
    uint32_t sow = (uint32_t)(wrow*64 + ((c4 ^ ((wrow>>1)&3))*16));
    size_t wg = (size_t)wrow*KDIM + c4*8;

    auto load_stage = [&](int stg, int kt) {
        uint32_t base = sb + (uint32_t)stg * OC_STG;
        int kpix = kt / 3;
        int poff = (kpix >> 2)*(HH*CH) + (kpix & 3)*CH + (kt - kpix*3)*32 + c4*8;
        CP_ASYNC16(base + so0,        g_hh + rb0 + poff);
        CP_ASYNC16(base + so1,        g_hh + rb1 + poff);
        CP_ASYNC16(base + 4096 + sow, g_woh + wg + kt*32);
        CP_COMMIT();
    };

    int lrow = lane & 15, lc = lane >> 4;
    uint32_t a_off[2], w_off[2][2];
    #pragma unroll
    for (int kh = 0; kh < 2; kh++) {
        int row = wid*16 + lrow;
        a_off[kh] = (uint32_t)(row*64 + (((kh*2 + lc) ^ ((row>>1)&3))*16));
        #pragma unroll
        for (int h = 0; h < 2; h++) {
            int wr2 = h*16 + lrow;
            w_off[h][kh] = (uint32_t)(wr2*64 + (((kh*2 + lc) ^ ((wr2>>1)&3))*16));
        }
    }

    float acc[4][4];
    #pragma unroll
    for (int i = 0; i < 4; i++)
        #pragma unroll
        for (int q = 0; q < 4; q++) acc[i][q] = 0.f;

    load_stage(0, 0); load_stage(1, 1); load_stage(2, 2);

    for (int kt = 0; kt < OC_NIT; kt++) {
        if (kt + 2 < OC_NIT) asm volatile("cp.async.wait_group 2;" ::: "memory");
        else                 asm volatile("cp.async.wait_group 0;" ::: "memory");
        __syncthreads();
        if (kt + 3 < OC_NIT) load_stage((kt+3) & 3, kt+3);

        uint32_t base = sb + (uint32_t)(kt & 3) * OC_STG;
        #pragma unroll
        for (int kh = 0; kh < 2; kh++) {
            uint32_t ah[4];
            LDSM4(ah, base + a_off[kh]);
            #pragma unroll
            for (int h = 0; h < 2; h++) {
                uint32_t wh[4];
                LDSM4(wh, base + 4096 + w_off[h][kh]);
                MMA16816(acc[h*2],   ah, wh[0], wh[2]);
                MMA16816(acc[h*2+1], ah, wh[1], wh[3]);
            }
        }
    }

    int rr = bm + wid*16 + (lane >> 2);
    #pragma unroll
    for (int nj = 0; nj < 4; nj++) {
        int col = (nj >> 1)*16 + (nj & 1)*8 + (lane & 3)*2;
        float b0v = offb[col], b1v = offb[col+1];
        *(float2*)&g_off[(size_t)rr*NOFF + col] =
            make_float2(acc[nj][0] + b0v, acc[nj][1] + b1v);
        *(float2*)&g_off[(size_t)(rr+8)*NOFF + col] =
            make_float2(acc[nj][2] + b0v, acc[nj][3] + b1v);
    }
}

// =====================================================================
// Kernel 4: bilinear sampling (fp16 src) -> fp16 A [m][k*96+c]
// One warp per m. lane = k*2 + half; each lane: one k, 48 channels,
// gathered via 6 x uint4 (LDG.128) per corner. Full 32-lane utilization.
// =====================================================================
__global__ __launch_bounds__(256) void sample_kernel()
{
    int m    = (blockIdx.x*256 + threadIdx.x) >> 5;
    int lane = threadIdx.x & 31;
    int k = lane >> 1, hhf = lane & 1;
    int b = m / SPA, s = m % SPA;
    int oh = s / HO, ow = s % HO;

    float offy = g_off[(size_t)m*NOFF + k*2];
    float offx = g_off[(size_t)m*NOFF + k*2 + 1];
    float py = (float)(oh*4 + (k >> 2)) + offy;
    float px = (float)(ow*4 + (k & 3)) + offx;
    float y0f = floorf(py), x0f = floorf(px);
    float wy = py - y0f, wx = px - x0f;
    int y0 = (int)y0f, x0 = (int)x0f;
    int y1 = y0 + 1,  x1 = x0 + 1;
    bool vy0 = (y0 >= 0) & (y0 < HH), vy1 = (y1 >= 0) & (y1 < HH);
    bool vx0 = (x0 >= 0) & (x0 < HH), vx1 = (x1 >= 0) & (x1 < HH);
    int cy0 = min(max(y0, 0), HH-1), cy1 = min(max(y1, 0), HH-1);
    int cx0 = min(max(x0, 0), HH-1), cx1 = min(max(x1, 0), HH-1);
    float q00 = (1.f-wy)*(1.f-wx) * (float)(vy0 && vx0);
    float q01 = (1.f-wy)*wx       * (float)(vy0 && vx1);
    float q10 = wy*(1.f-wx)       * (float)(vy1 && vx0);
    float q11 = wy*wx             * (float)(vy1 && vx1);

    const __half* hb = g_hh + (size_t)b*HH*HH*CH + hhf*48;
    const __half* p00 = hb + (cy0*HH + cx0)*CH;
    const __half* p01 = hb + (cy0*HH + cx1)*CH;
    const __half* p10 = hb + (cy1*HH + cx0)*CH;
    const __half* p11 = hb + (cy1*HH + cx1)*CH;
    __half* ob = g_Af + (size_t)m*KDIM + k*CH + hhf*48;

    #pragma unroll
    for (int j = 0; j < 6; j++) {
        uint4 u00 = *(const uint4*)(p00 + j*8);
        uint4 u01 = *(const uint4*)(p01 + j*8);
        uint4 u10 = *(const uint4*)(p10 + j*8);
        uint4 u11 = *(const uint4*)(p11 + j*8);
        uint4 o;
        const uint32_t* a4 = &u00.x;
        const uint32_t* b4 = &u01.x;
        const uint32_t* c4 = &u10.x;
        const uint32_t* d4 = &u11.x;
        uint32_t* o4 = &o.x;
        #pragma unroll
        for (int t = 0; t < 4; t++) {
            float2 av = __half22float2(*(const __half2*)&a4[t]);
            float2 bv = __half22float2(*(const __half2*)&b4[t]);
            float2 cv = __half22float2(*(const __half2*)&c4[t]);
            float2 dv = __half22float2(*(const __half2*)&d4[t]);
            float r0 = av.x*q00 + bv.x*q01 + cv.x*q10 + dv.x*q11;
            float r1 = av.y*q00 + bv.y*q01 + cv.y*q10 + dv.y*q11;
            __half2 hv = __floats2half2_rn(r0, r1);
            o4[t] = *(uint32_t*)&hv;
        }
        *(uint4*)(ob + j*8) = o;
    }
}

// =====================================================================
// Kernel 5: single-pass fp16 GEMM + BN2 + LeakyReLU
// CTA 128x128, BK=32, 8 warps (warp 64x32), 4-stage cp.async, 2 CTA/SM
// =====================================================================
#define BK       32
#define NIT      48
#define OFF_B    8192u
#define STG_BYTES 16384u
#define NSTAGE   4
#define SMEM_GEMM (NSTAGE*STG_BYTES + 1024)

__global__ __launch_bounds__(256, 2) void gemm_mma_kernel(
    const float* __restrict__ dcnb, const float* __restrict__ g2,
    const float* __restrict__ b2,   const float* __restrict__ bn2m,
    const float* __restrict__ v2,   float* __restrict__ out)
{
    extern __shared__ char smem[];
    uint32_t sb = smem_to_u32(smem);
    float* sScale = (float*)(smem + NSTAGE*STG_BYTES);
    float* sBeta  = sScale + 128;

    int tid  = threadIdx.x;
    int lane = tid & 31, wid = tid >> 5;
    int wm = wid & 1, wn = wid >> 1;       // 2 x 4 warp grid, warp 64x32
    int bm = blockIdx.y * 128;
    int bn = blockIdx.x * 128;

    if (tid < 128) {
        int n = bn + tid;
        float inv = g2[n] * rsqrtf(v2[n] + 1e-5f);
        sScale[tid] = inv;
        sBeta[tid]  = (dcnb[n] - bn2m[n])*inv + b2[n];
    }

    auto load_stage = [&](int stg, int kt) {
        uint32_t base = sb + (uint32_t)stg * STG_BYTES;
        int ks = kt * BK;
        #pragma unroll
        for (int i = 0; i < 2; i++) {             // A: 512 chunks
            int id = tid + i*256;
            int row = id >> 2, c = id & 3;
            uint32_t so = (uint32_t)(row*64 + ((c ^ ((row>>1)&3))*16));
            CP_ASYNC16(base + so, g_Af + (size_t)(bm+row)*KDIM + ks + c*8);
        }
        #pragma unroll
        for (int i = 0; i < 2; i++) {             // B: 512 chunks
            int id = tid + i*256;
            int row = id >> 2, c = id & 3;
            uint32_t so = (uint32_t)(row*64 + ((c ^ ((row>>1)&3))*16));
            CP_ASYNC16(base + OFF_B + so, g_Bhi + (size_t)(bn+row)*KDIM + ks + c*8);
        }
        CP_COMMIT();
    };

    int lrow = lane & 15, lc = lane >> 4;
    uint32_t a_off[4][2], b_off[2][2];
    #pragma unroll
    for (int mi = 0; mi < 4; mi++) {
        int row = wm*64 + mi*16 + lrow;
        int rs = (row >> 1) & 3;
        #pragma unroll
        for (int kh = 0; kh < 2; kh++)
            a_off[mi][kh] = (uint32_t)(row*64 + (((kh*2 + lc) ^ rs) * 16));
    }
    #pragma unroll
    for (int nb = 0; nb < 2; nb++) {
        int row = wn*32 + nb*16 + lrow;
        int rs = (row >> 1) & 3;
        #pragma unroll
        for (int kh = 0; kh < 2; kh++)
            b_off[nb][kh] = (uint32_t)(row*64 + (((kh*2 + lc) ^ rs) * 16));
    }

    float acc[4][4][4];
    #pragma unroll
    for (int i = 0; i < 4; i++)
        #pragma unroll
        for (int j = 0; j < 4; j++)
            #pragma unroll
            for (int q = 0; q < 4; q++) acc[i][j][q] = 0.f;

    load_stage(0, 0); load_stage(1, 1); load_stage(2, 2);

    for (int kt = 0; kt < NIT; kt++) {
        if (kt + 2 < NIT) asm volatile("cp.async.wait_group 2;" ::: "memory");
        else              asm volatile("cp.async.wait_group 0;" ::: "memory");
        __syncthreads();
        if (kt + 3 < NIT) load_stage((kt+3) & 3, kt+3);

        uint32_t base = sb + (uint32_t)(kt & 3) * STG_BYTES;
        #pragma unroll
        for (int kh = 0; kh < 2; kh++) {
            uint32_t a[4][4];
            #pragma unroll
            for (int mi = 0; mi < 4; mi++)
                LDSM4(a[mi], base + a_off[mi][kh]);
            #pragma unroll
            for (int nb = 0; nb < 2; nb++) {
                uint32_t bh[4];
                LDSM4(bh, base + OFF_B + b_off[nb][kh]);
                #pragma unroll
                for (int mi = 0; mi < 4; mi++) {
                    MMA16816(acc[mi][2*nb],   a[mi], bh[0], bh[2]);
                    MMA16816(acc[mi][2*nb+1], a[mi], bh[1], bh[3]);
                }
            }
        }
    }

    // ---- epilogue: BN2 + LeakyReLU, final (B, HoWo, C) layout ----
    #pragma unroll
    for (int mi = 0; mi < 4; mi++) {
        int r0 = bm + wm*64 + mi*16 + (lane >> 2);
        #pragma unroll
        for (int nj = 0; nj < 4; nj++) {
            int colL = wn*32 + nj*8 + (lane & 3)*2;
            float s0 = sScale[colL],   s1 = sScale[colL+1];
            float e0 = sBeta[colL],    e1 = sBeta[colL+1];
            float v0 = acc[mi][nj][0]*s0 + e0;
            float v1 = acc[mi][nj][1]*s1 + e1;
            float v2 = acc[mi][nj][2]*s0 + e0;
            float v3 = acc[mi][nj][3]*s1 + e1;
            v0 = (v0 >= 0.f) ? v0 : 0.01f*v0;
            v1 = (v1 >= 0.f) ? v1 : 0.01f*v1;
            v2 = (v2 >= 0.f) ? v2 : 0.01f*v2;
            v3 = (v3 >= 0.f) ? v3 : 0.01f*v3;
            *(float2*)&out[(size_t)r0*ND + bn + colL]     = make_float2(v0, v1);
            *(float2*)&out[(size_t)(r0+8)*ND + bn + colL] = make_float2(v2, v3);
        }
    }
}

// =====================================================================
extern "C" void kernel_launch(void* const* d_in, const int* in_sizes, int n_in,
                              void* d_out, int out_size)
{
    const float* x      = (const float*)d_in[0];
    const float* stem_w = (const float*)d_in[1];
    const float* stem_b = (const float*)d_in[2];
    const float* bn1_g  = (const float*)d_in[3];
    const float* bn1_b  = (const float*)d_in[4];
    const float* bn1_m  = (const float*)d_in[5];
    const float* bn1_v  = (const float*)d_in[6];
    const float* off_w  = (const float*)d_in[7];
    const float* off_b  = (const float*)d_in[8];
    const float* dcn_w  = (const float*)d_in[9];
    const float* dcn_b  = (const float*)d_in[10];
    const float* bn2_g  = (const float*)d_in[11];
    const float* bn2_b  = (const float*)d_in[12];
    const float* bn2_m  = (const float*)d_in[13];
    const float* bn2_v  = (const float*)d_in[14];
    float* out = (float*)d_out;

    cudaFuncSetAttribute(gemm_mma_kernel,
                         cudaFuncAttributeMaxDynamicSharedMemorySize, SMEM_GEMM);
    cudaFuncSetAttribute(offconv_mma_kernel,
                         cudaFuncAttributeMaxDynamicSharedMemorySize, SMEM_OC);

    stem_kernel<<<NB*HH, 192>>>(x, stem_w, stem_b, bn1_g, bn1_b, bn1_m, bn1_v);
    prep_kernel<<<(ND*KDIM + 255)/256, 256>>>(dcn_w, off_w);
    offconv_mma_kernel<<<MM2/64, 128, SMEM_OC>>>(off_b);
    sample_kernel<<<MM2*32/256, 256>>>();
    gemm_mma_kernel<<<dim3(ND/128, MM2/128), 256, SMEM_GEMM>>>(
        dcn_b, bn2_g, bn2_b, bn2_m, bn2_v, out);
}

// round 8
// speedup vs baseline: 3.4839x; 1.0336x over previous
#include <cuda_runtime.h>
#include <cuda_fp16.h>
#include <cstdint>

// ---------------- problem constants ----------------
#define NB    64
#define CIN   3
#define HIN   224
#define CH    96
#define HH    56
#define HO    14
#define SPA   196
#define MM2   12544   // GEMM M
#define KDIM  1536    // GEMM K
#define ND    768     // GEMM N
#define NOFF  32

// ---------------- scratch (device globals) ----------------
__device__ __half g_hh[(size_t)NB*HH*HH*CH];   // stem output fp16 NHWC
__device__ float  g_off[(size_t)MM2*NOFF];     // offsets [m][32]
__device__ __half g_woh[(size_t)NOFF*KDIM];    // off_w [n][k*96+c] fp16
__device__ __half g_Af [(size_t)MM2*KDIM];     // sampled A, fp16
__device__ __half g_Bhi[(size_t)ND*KDIM];      // dcn_w [o][k*96+c] fp16

// ==================== PTX helpers (plain-target safe) ====================
__device__ __forceinline__ uint32_t smem_to_u32(const void* p) {
    uint32_t a;
    asm("{ .reg .u64 t; cvta.to.shared.u64 t, %1; cvt.u32.u64 %0, t; }" : "=r"(a) : "l"(p));
    return a;
}
#define CP_ASYNC16(s, g) \
    asm volatile("cp.async.cg.shared.global [%0], [%1], 16;" :: "r"(s), "l"(g) : "memory")
#define CP_COMMIT() asm volatile("cp.async.commit_group;" ::: "memory")
#define LDSM4(r, a) \
    asm volatile("ldmatrix.sync.aligned.m8n8.x4.shared.b16 {%0,%1,%2,%3}, [%4];" \
        : "=r"((r)[0]), "=r"((r)[1]), "=r"((r)[2]), "=r"((r)[3]) : "r"(a))
#define MMA16816(d, a, b0v, b1v) \
    asm volatile("mma.sync.aligned.m16n8k16.row.col.f32.f16.f16.f32 " \
        "{%0,%1,%2,%3},{%4,%5,%6,%7},{%8,%9},{%0,%1,%2,%3};" \
        : "+f"((d)[0]), "+f"((d)[1]), "+f"((d)[2]), "+f"((d)[3]) \
        : "r"((a)[0]), "r"((a)[1]), "r"((a)[2]), "r"((a)[3]), "r"(b0v), "r"(b1v))

// =====================================================================
// Kernel 1: stem conv + BN1 + LeakyReLU -> g_hh (fp16 NHWC)
// =====================================================================
__global__ __launch_bounds__(192) void stem_kernel(
    const float* __restrict__ x, const float* __restrict__ w,
    const float* __restrict__ bias,
    const float* __restrict__ g1, const float* __restrict__ b1,
    const float* __restrict__ m1, const float* __restrict__ v1)
{
    int b  = blockIdx.x / HH;
    int oh = blockIdx.x % HH;
    __shared__ float sx[CIN*4*HIN];
    __shared__ float sinv[CH], sbeta[CH];
    int tid = threadIdx.x;

    for (int i = tid; i < CIN*4*HIN; i += 192) {
        int j = i / HIN, col = i % HIN;
        int c = j >> 2, kh = j & 3;
        sx[i] = x[((size_t)(b*CIN + c)*HIN + (4*oh + kh))*HIN + col];
    }
    if (tid < CH) {
        float inv = g1[tid] * rsqrtf(v1[tid] + 1e-5f);
        sinv[tid]  = inv;
        sbeta[tid] = (bias[tid] - m1[tid]) * inv + b1[tid];
    }
    __syncthreads();

    int o = tid % CH, owb = tid / CH;
    float4 wr[12];
    #pragma unroll
    for (int j = 0; j < 12; j++) wr[j] = *(const float4*)&w[o*48 + j*4];
    float inv = sinv[o], beta = sbeta[o];

    for (int ow = owb; ow < HH; ow += 2) {
        float acc = 0.f;
        #pragma unroll
        for (int j = 0; j < 12; j++) {
            float4 xv = *(const float4*)&sx[j*HIN + 4*ow];
            acc += xv.x*wr[j].x + xv.y*wr[j].y + xv.z*wr[j].z + xv.w*wr[j].w;
        }
        float val = acc*inv + beta;
        val = (val >= 0.f) ? val : 0.01f*val;
        g_hh[((size_t)(b*HH + oh)*HH + ow)*CH + o] = __float2half(val);
    }
}

// =====================================================================
// Kernel 2: weight prep (dcn_w fp16, off_w fp16, both [n][k*96+c])
// =====================================================================
__global__ __launch_bounds__(256) void prep_kernel(
    const float* __restrict__ wd, const float* __restrict__ wo)
{
    int i = blockIdx.x*256 + threadIdx.x;
    if (i < ND*KDIM) {
        int o = i / KDIM, r = i % KDIM;
        int k = r / CH, c = r % CH;
        g_Bhi[i] = __float2half(wd[(size_t)o*KDIM + c*16 + k]);
    }
    if (i < NOFF*KDIM) {
        int n = i / KDIM, r = i % KDIM;
        int k = r / CH, c = r % CH;
        g_woh[i] = __float2half(wo[(size_t)n*KDIM + c*16 + k]);
    }
}

// =====================================================================
// Kernel 3: offset conv via mma.sync, single-pass fp16
// M-tile 64, N=32, BK=32, 4 warps, 4-stage cp.async, im2col on the fly
// =====================================================================
#define OC_NIT 48
#define OC_STG 6144u     // Ah 4K | Wh 2K
#define SMEM_OC (4*OC_STG)

__global__ __launch_bounds__(128, 1) void offconv_mma_kernel(const float* __restrict__ offb)
{
    extern __shared__ char smem[];
    uint32_t sb = smem_to_u32(smem);
    int tid = threadIdx.x;
    int lane = tid & 31, wid = tid >> 5;
    int bm = blockIdx.x * 64;

    int c4 = tid & 3;
    int r0 = tid >> 2, r1 = r0 + 32;
    int m0 = bm + r0, m1v = bm + r1;
    int b0 = m0 / SPA, s0 = m0 % SPA;
    int b1 = m1v / SPA, s1 = m1v % SPA;
    size_t rb0 = ((size_t)(b0*HH + (s0/HO)*4)*HH + (s0%HO)*4)*CH;
    size_t rb1 = ((size_t)(b1*HH + (s1/HO)*4)*HH + (s1%HO)*4)*CH;
    uint32_t so0 = (uint32_t)(r0*64 + ((c4 ^ ((r0>>1)&3))*16));
    uint32_t so1 = (uint32_t)(r1*64 + ((c4 ^ ((r1>>1)&3))*16));
    int wrow = tid >> 2;
    uint32_t sow = (uint32_t)(wrow*64 + ((c4 ^ ((wrow>>1)&3))*16));
    size_t wg = (size_t)wrow*KDIM + c4*8;

    auto load_stage = [&](int stg, int kt) {
        uint32_t base = sb + (uint32_t)stg * OC_STG;
        int kpix = kt / 3;
        int poff = (kpix >> 2)*(HH*CH) + (kpix & 3)*CH + (kt - kpix*3)*32 + c4*8;
        CP_ASYNC16(base + so0,        g_hh + rb0 + poff);
        CP_ASYNC16(base + so1,        g_hh + rb1 + poff);
        CP_ASYNC16(base + 4096 + sow, g_woh + wg + kt*32);
        CP_COMMIT();
    };

    int lrow = lane & 15, lc = lane >> 4;
    uint32_t a_off[2], w_off[2][2];
    #pragma unroll
    for (int kh = 0; kh < 2; kh++) {
        int row = wid*16 + lrow;
        a_off[kh] = (uint32_t)(row*64 + (((kh*2 + lc) ^ ((row>>1)&3))*16));
        #pragma unroll
        for (int h = 0; h < 2; h++) {
            int wr2 = h*16 + lrow;
            w_off[h][kh] = (uint32_t)(wr2*64 + (((kh*2 + lc) ^ ((wr2>>1)&3))*16));
        }
    }

    float acc[4][4];
    #pragma unroll
    for (int i = 0; i < 4; i++)
        #pragma unroll
        for (int q = 0; q < 4; q++) acc[i][q] = 0.f;

    load_stage(0, 0); load_stage(1, 1); load_stage(2, 2);

    for (int kt = 0; kt < OC_NIT; kt++) {
        if (kt + 2 < OC_NIT) asm volatile("cp.async.wait_group 2;" ::: "memory");
        else                 asm volatile("cp.async.wait_group 0;" ::: "memory");
        __syncthreads();
        if (kt + 3 < OC_NIT) load_stage((kt+3) & 3, kt+3);

        uint32_t base = sb + (uint32_t)(kt & 3) * OC_STG;
        #pragma unroll
        for (int kh = 0; kh < 2; kh++) {
            uint32_t ah[4];
            LDSM4(ah, base + a_off[kh]);
            #pragma unroll
            for (int h = 0; h < 2; h++) {
                uint32_t wh[4];
                LDSM4(wh, base + 4096 + w_off[h][kh]);
                MMA16816(acc[h*2],   ah, wh[0], wh[2]);
                MMA16816(acc[h*2+1], ah, wh[1], wh[3]);
            }
        }
    }

    int rr = bm + wid*16 + (lane >> 2);
    #pragma unroll
    for (int nj = 0; nj < 4; nj++) {
        int col = (nj >> 1)*16 + (nj & 1)*8 + (lane & 3)*2;
        float b0v = offb[col], b1v = offb[col+1];
        *(float2*)&g_off[(size_t)rr*NOFF + col] =
            make_float2(acc[nj][0] + b0v, acc[nj][1] + b1v);
        *(float2*)&g_off[(size_t)(rr+8)*NOFF + col] =
            make_float2(acc[nj][2] + b0v, acc[nj][3] + b1v);
    }
}

// =====================================================================
// Kernel 4: bilinear sampling (fp16 src) -> fp16 A [m][k*96+c]
// One warp per m. Lanes 0-15 precompute 16 k-prologues; then 16 dense
// iterations with shfl broadcast, lanes 0-23 x 4 channels (coalesced).
// (R5 formulation — measured fastest.)
// =====================================================================
__global__ __launch_bounds__(256) void sample_kernel()
{
    int m    = (blockIdx.x*256 + threadIdx.x) >> 5;
    int lane = threadIdx.x & 31;
    int b = m / SPA, s = m % SPA;
    int oh = s / HO, ow = s % HO;

    int e00 = 0, e01 = 0, e10 = 0, e11 = 0;
    float w00 = 0.f, w01 = 0.f, w10 = 0.f, w11 = 0.f;
    if (lane < 16) {
        int k = lane;
        float offy = g_off[(size_t)m*NOFF + k*2];
        float offx = g_off[(size_t)m*NOFF + k*2 + 1];
        float py = (float)(oh*4 + (k >> 2)) + offy;
        float px = (float)(ow*4 + (k & 3)) + offx;
        float y0f = floorf(py), x0f = floorf(px);
        float wy = py - y0f, wx = px - x0f;
        int y0 = (int)y0f, x0 = (int)x0f;
        int y1 = y0 + 1,  x1 = x0 + 1;
        bool vy0 = (y0 >= 0) & (y0 < HH), vy1 = (y1 >= 0) & (y1 < HH);
        bool vx0 = (x0 >= 0) & (x0 < HH), vx1 = (x1 >= 0) & (x1 < HH);
        int cy0 = min(max(y0, 0), HH-1), cy1 = min(max(y1, 0), HH-1);
        int cx0 = min(max(x0, 0), HH-1), cx1 = min(max(x1, 0), HH-1);
        e00 = (cy0*HH + cx0)*CH;
        e01 = (cy0*HH + cx1)*CH;
        e10 = (cy1*HH + cx0)*CH;
        e11 = (cy1*HH + cx1)*CH;
        w00 = (1.f-wy)*(1.f-wx) * (float)(vy0 && vx0);
        w01 = (1.f-wy)*wx       * (float)(vy0 && vx1);
        w10 = wy*(1.f-wx)       * (float)(vy1 && vx0);
        w11 = wy*wx             * (float)(vy1 && vx1);
    }

    const __half* hb = g_hh + (size_t)b*HH*HH*CH;
    __half* ob = g_Af + (size_t)m*KDIM;
    int c = (lane < 24) ? lane*4 : 0;

    #pragma unroll 4
    for (int k = 0; k < 16; k++) {
        int   f00 = __shfl_sync(0xFFFFFFFFu, e00, k);
        int   f01 = __shfl_sync(0xFFFFFFFFu, e01, k);
        int   f10 = __shfl_sync(0xFFFFFFFFu, e10, k);
        int   f11 = __shfl_sync(0xFFFFFFFFu, e11, k);
        float q00 = __shfl_sync(0xFFFFFFFFu, w00, k);
        float q01 = __shfl_sync(0xFFFFFFFFu, w01, k);
        float q10 = __shfl_sync(0xFFFFFFFFu, w10, k);
        float q11 = __shfl_sync(0xFFFFFFFFu, w11, k);
        if (lane < 24) {
            uint2 u00 = *(const uint2*)(hb + f00 + c);
            uint2 u01 = *(const uint2*)(hb + f01 + c);
            uint2 u10 = *(const uint2*)(hb + f10 + c);
            uint2 u11 = *(const uint2*)(hb + f11 + c);
            float2 a0 = __half22float2(*(__half2*)&u00.x);
            float2 a1 = __half22float2(*(__half2*)&u00.y);
            float2 b0 = __half22float2(*(__half2*)&u01.x);
            float2 b1 = __half22float2(*(__half2*)&u01.y);
            float2 c0 = __half22float2(*(__half2*)&u10.x);
            float2 c1 = __half22float2(*(__half2*)&u10.y);
            float2 d0 = __half22float2(*(__half2*)&u11.x);
            float2 d1 = __half22float2(*(__half2*)&u11.y);
            float r0 = a0.x*q00 + b0.x*q01 + c0.x*q10 + d0.x*q11;
            float r1 = a0.y*q00 + b0.y*q01 + c0.y*q10 + d0.y*q11;
            float r2 = a1.x*q00 + b1.x*q01 + c1.x*q10 + d1.x*q11;
            float r3 = a1.y*q00 + b1.y*q01 + c1.y*q10 + d1.y*q11;
            __half2 h0 = __floats2half2_rn(r0, r1);
            __half2 h1 = __floats2half2_rn(r2, r3);
            uint2 o;
            o.x = *(uint32_t*)&h0;
            o.y = *(uint32_t*)&h1;
            *(uint2*)(ob + k*CH + c) = o;
        }
    }
}

// =====================================================================
// Kernel 5: single-pass fp16 GEMM + BN2 + LeakyReLU
// CTA 128x128, BK=64, 8 warps (warp 64x32), 3-stage cp.async, 2 CTA/SM
// SMEM stage: A 16K (128x64, 128B rows, SW128 xor row&7) | B 16K
// =====================================================================
#define BK       64
#define NIT      24
#define OFF_B    16384u
#define STG_BYTES 32768u
#define NSTAGE   3
#define SMEM_GEMM (NSTAGE*STG_BYTES + 1024)

__global__ __launch_bounds__(256, 2) void gemm_mma_kernel(
    const float* __restrict__ dcnb, const float* __restrict__ g2,
    const float* __restrict__ b2,   const float* __restrict__ bn2m,
    const float* __restrict__ v2,   float* __restrict__ out)
{
    extern __shared__ char smem[];
    uint32_t sb = smem_to_u32(smem);
    float* sScale = (float*)(smem + NSTAGE*STG_BYTES);
    float* sBeta  = sScale + 128;

    int tid  = threadIdx.x;
    int lane = tid & 31, wid = tid >> 5;
    int wm = wid & 1, wn = wid >> 1;       // 2 x 4 warp grid, warp 64x32
    int bm = blockIdx.y * 128;
    int bn = blockIdx.x * 128;

    if (tid < 128) {
        int n = bn + tid;
        float inv = g2[n] * rsqrtf(v2[n] + 1e-5f);
        sScale[tid] = inv;
        sBeta[tid]  = (dcnb[n] - bn2m[n])*inv + b2[n];
    }

    // loader: 128 rows x 8 chunks (16B) each for A and B; 4+4 per thread
    int lrw = tid >> 1;                       // used pairwise below
    (void)lrw;
    auto load_stage = [&](int stg, int kt) {
        uint32_t base = sb + (uint32_t)stg * STG_BYTES;
        int ks = kt * BK;
        #pragma unroll
        for (int i = 0; i < 4; i++) {             // A: 1024 chunks
            int id = tid + i*256;
            int row = id >> 3, c = id & 7;
            uint32_t so = (uint32_t)(row*128 + ((c ^ (row & 7))*16));
            CP_ASYNC16(base + so, g_Af + (size_t)(bm+row)*KDIM + ks + c*8);
        }
        #pragma unroll
        for (int i = 0; i < 4; i++) {             // B: 1024 chunks
            int id = tid + i*256;
            int row = id >> 3, c = id & 7;
            uint32_t so = (uint32_t)(row*128 + ((c ^ (row & 7))*16));
            CP_ASYNC16(base + OFF_B + so, g_Bhi + (size_t)(bn+row)*KDIM + ks + c*8);
        }
        CP_COMMIT();
    };

    // ldmatrix base/rs (offset recomputed per kh to save registers)
    int lrow = lane & 15, lc = lane >> 4;
    uint32_t a_base[4]; int a_rs[4];
    uint32_t b_base[2]; int b_rs[2];
    #pragma unroll
    for (int mi = 0; mi < 4; mi++) {
        int row = wm*64 + mi*16 + lrow;
        a_base[mi] = (uint32_t)(row*128);
        a_rs[mi]   = row & 7;
    }
    #pragma unroll
    for (int nb = 0; nb < 2; nb++) {
        int row = wn*32 + nb*16 + lrow;
        b_base[nb] = (uint32_t)(row*128);
        b_rs[nb]   = row & 7;
    }

    float acc[4][4][4];
    #pragma unroll
    for (int i = 0; i < 4; i++)
        #pragma unroll
        for (int j = 0; j < 4; j++)
            #pragma unroll
            for (int q = 0; q < 4; q++) acc[i][j][q] = 0.f;

    load_stage(0, 0); load_stage(1, 1);

    for (int kt = 0; kt < NIT; kt++) {
        if (kt + 1 < NIT) asm volatile("cp.async.wait_group 1;" ::: "memory");
        else              asm volatile("cp.async.wait_group 0;" ::: "memory");
        __syncthreads();
        if (kt + 2 < NIT) load_stage((kt+2) % NSTAGE, kt+2);

        uint32_t base = sb + (uint32_t)(kt % NSTAGE) * STG_BYTES;
        #pragma unroll
        for (int kh = 0; kh < 4; kh++) {
            int ch = kh*2 + lc;
            uint32_t a[4][4];
            #pragma unroll
            for (int mi = 0; mi < 4; mi++)
                LDSM4(a[mi], base + a_base[mi] + (uint32_t)(((ch ^ a_rs[mi]) << 4)));
            #pragma unroll
            for (int nb = 0; nb < 2; nb++) {
                uint32_t bh[4];
                LDSM4(bh, base + OFF_B + b_base[nb] + (uint32_t)(((ch ^ b_rs[nb]) << 4)));
                #pragma unroll
                for (int mi = 0; mi < 4; mi++) {
                    MMA16816(acc[mi][2*nb],   a[mi], bh[0], bh[2]);
                    MMA16816(acc[mi][2*nb+1], a[mi], bh[1], bh[3]);
                }
            }
        }
    }

    // ---- epilogue: BN2 + LeakyReLU, final (B, HoWo, C) layout ----
    #pragma unroll
    for (int mi = 0; mi < 4; mi++) {
        int r0 = bm + wm*64 + mi*16 + (lane >> 2);
        #pragma unroll
        for (int nj = 0; nj < 4; nj++) {
            int colL = wn*32 + nj*8 + (lane & 3)*2;
            float s0 = sScale[colL],   s1 = sScale[colL+1];
            float e0 = sBeta[colL],    e1 = sBeta[colL+1];
            float v0 = acc[mi][nj][0]*s0 + e0;
            float v1 = acc[mi][nj][1]*s1 + e1;
            float v2 = acc[mi][nj][2]*s0 + e0;
            float v3 = acc[mi][nj][3]*s1 + e1;
            v0 = (v0 >= 0.f) ? v0 : 0.01f*v0;
            v1 = (v1 >= 0.f) ? v1 : 0.01f*v1;
            v2 = (v2 >= 0.f) ? v2 : 0.01f*v2;
            v3 = (v3 >= 0.f) ? v3 : 0.01f*v3;
            *(float2*)&out[(size_t)r0*ND + bn + colL]     = make_float2(v0, v1);
            *(float2*)&out[(size_t)(r0+8)*ND + bn + colL] = make_float2(v2, v3);
        }
    }
}

// =====================================================================
extern "C" void kernel_launch(void* const* d_in, const int* in_sizes, int n_in,
                              void* d_out, int out_size)
{
    const float* x      = (const float*)d_in[0];
    const float* stem_w = (const float*)d_in[1];
    const float* stem_b = (const float*)d_in[2];
    const float* bn1_g  = (const float*)d_in[3];
    const float* bn1_b  = (const float*)d_in[4];
    const float* bn1_m  = (const float*)d_in[5];
    const float* bn1_v  = (const float*)d_in[6];
    const float* off_w  = (const float*)d_in[7];
    const float* off_b  = (const float*)d_in[8];
    const float* dcn_w  = (const float*)d_in[9];
    const float* dcn_b  = (const float*)d_in[10];
    const float* bn2_g  = (const float*)d_in[11];
    const float* bn2_b  = (const float*)d_in[12];
    const float* bn2_m  = (const float*)d_in[13];
    const float* bn2_v  = (const float*)d_in[14];
    float* out = (float*)d_out;

    cudaFuncSetAttribute(gemm_mma_kernel,
                         cudaFuncAttributeMaxDynamicSharedMemorySize, SMEM_GEMM);
    cudaFuncSetAttribute(offconv_mma_kernel,
                         cudaFuncAttributeMaxDynamicSharedMemorySize, SMEM_OC);

    stem_kernel<<<NB*HH, 192>>>(x, stem_w, stem_b, bn1_g, bn1_b, bn1_m, bn1_v);
    prep_kernel<<<(ND*KDIM + 255)/256, 256>>>(dcn_w, off_w);
    offconv_mma_kernel<<<MM2/64, 128, SMEM_OC>>>(off_b);
    sample_kernel<<<MM2*32/256, 256>>>();
    gemm_mma_kernel<<<dim3(ND/128, MM2/128), 256, SMEM_GEMM>>>(
        dcn_b, bn2_g, bn2_b, bn2_m, bn2_v, out);
}

// round 9
// speedup vs baseline: 5.6988x; 1.6358x over previous
#include <cuda_runtime.h>
#include <cuda_fp16.h>
#include <cstdint>

// ---------------- problem constants ----------------
#define NB    64
#define CIN   3
#define HIN   224
#define CH    96
#define HH    56
#define SH    3136    // 56*56
#define HO    14
#define SPA   196
#define MM2   12544   // GEMM M
#define KDIM  1536    // GEMM K
#define ND    768     // GEMM N
#define NOFF  32

// ---------------- scratch (device globals) ----------------
__device__ __half g_hh[(size_t)NB*HH*HH*CH];   // stem output fp16 NHWC
__device__ float  g_off[(size_t)MM2*NOFF];     // offsets [m][32]
__device__ __half g_woh[(size_t)NOFF*KDIM];    // off_w [n][k*96+c] fp16
__device__ __half g_Af [(size_t)MM2*KDIM];     // sampled A, fp16
__device__ __half g_Bhi[(size_t)ND*KDIM];      // dcn_w [o][k*96+c] fp16

// ==================== PTX helpers (plain-target safe) ====================
__device__ __forceinline__ uint32_t smem_to_u32(const void* p) {
    uint32_t a;
    asm("{ .reg .u64 t; cvta.to.shared.u64 t, %1; cvt.u32.u64 %0, t; }" : "=r"(a) : "l"(p));
    return a;
}
#define CP_ASYNC16(s, g) \
    asm volatile("cp.async.cg.shared.global [%0], [%1], 16;" :: "r"(s), "l"(g) : "memory")
#define CP_COMMIT() asm volatile("cp.async.commit_group;" ::: "memory")
#define LDSM4(r, a) \
    asm volatile("ldmatrix.sync.aligned.m8n8.x4.shared.b16 {%0,%1,%2,%3}, [%4];" \
        : "=r"((r)[0]), "=r"((r)[1]), "=r"((r)[2]), "=r"((r)[3]) : "r"(a))
#define MMA16816(d, a, b0v, b1v) \
    asm volatile("mma.sync.aligned.m16n8k16.row.col.f32.f16.f16.f32 " \
        "{%0,%1,%2,%3},{%4,%5,%6,%7},{%8,%9},{%0,%1,%2,%3};" \
        : "+f"((d)[0]), "+f"((d)[1]), "+f"((d)[2]), "+f"((d)[3]) \
        : "r"((a)[0]), "r"((a)[1]), "r"((a)[2]), "r"((a)[3]), "r"(b0v), "r"(b1v))

// =====================================================================
// Kernel 1: stem patchify GEMM via mma.sync (M=200704, N=96, K=48)
// CTA: 128 rows x 96 cols, 4 warps (warp 32x96). fp32->fp16 in-kernel.
// SMEM: A' 16K (128 rows x 128B swizzled) | B' 12K (96 rows x 128B) | BN
// =====================================================================
#define SMEM_ST (16384 + 12288 + 1024)

__global__ __launch_bounds__(128) void stem_mma_kernel(
    const float* __restrict__ x, const float* __restrict__ w,
    const float* __restrict__ bias,
    const float* __restrict__ g1, const float* __restrict__ b1,
    const float* __restrict__ m1, const float* __restrict__ v1)
{
    extern __shared__ char smem[];
    uint32_t sb = smem_to_u32(smem);
    char* sA = smem;
    char* sB = smem + 16384;
    float* sScale = (float*)(smem + 28672);
    float* sBeta  = (float*)(smem + 28672 + 512);
    int tid = threadIdx.x, lane = tid & 31, wid = tid >> 5;
    int bm = blockIdx.x * 128;

    if (tid < CH) {
        float inv = g1[tid] * rsqrtf(v1[tid] + 1e-5f);
        sScale[tid] = inv;
        sBeta[tid]  = (bias[tid] - m1[tid]) * inv + b1[tid];
    }

    // ---- B': convert stem_w [96][48] fp32 -> fp16 swizzled (576 tasks) ----
    #pragma unroll
    for (int i = 0; i < 5; i++) {
        int tsk = tid + i*128;
        if (tsk < 576) {
            int o = tsk / 6, jj = tsk % 6;
            const float* wp = w + o*48 + jj*8;
            float4 f0 = *(const float4*)wp;
            float4 f1 = *(const float4*)(wp + 4);
            __half2 h0 = __floats2half2_rn(f0.x, f0.y);
            __half2 h1 = __floats2half2_rn(f0.z, f0.w);
            __half2 h2 = __floats2half2_rn(f1.x, f1.y);
            __half2 h3 = __floats2half2_rn(f1.z, f1.w);
            uint4 u;
            u.x = *(uint32_t*)&h0; u.y = *(uint32_t*)&h1;
            u.z = *(uint32_t*)&h2; u.w = *(uint32_t*)&h3;
            *(uint4*)(sB + o*128 + ((jj ^ (o & 7)) << 4)) = u;
        }
    }

    // ---- A': load x patches, convert, store swizzled (768 tasks) ----
    #pragma unroll
    for (int i = 0; i < 6; i++) {
        int tsk = tid + i*128;
        int jj = tsk >> 7, r = tsk & 127;
        int m = bm + r;
        int b = m / SH, s = m % SH;
        int oh = s / HH, ow = s % HH;
        int p0 = 2*jj, p1 = p0 + 1;               // p = c*4 + kh
        const float* x0 = x + ((size_t)(b*CIN + (p0 >> 2))*HIN + 4*oh + (p0 & 3))*HIN + 4*ow;
        const float* x1 = x + ((size_t)(b*CIN + (p1 >> 2))*HIN + 4*oh + (p1 & 3))*HIN + 4*ow;
        float4 f0 = *(const float4*)x0;
        float4 f1 = *(const float4*)x1;
        __half2 h0 = __floats2half2_rn(f0.x, f0.y);
        __half2 h1 = __floats2half2_rn(f0.z, f0.w);
        __half2 h2 = __floats2half2_rn(f1.x, f1.y);
        __half2 h3 = __floats2half2_rn(f1.z, f1.w);
        uint4 u;
        u.x = *(uint32_t*)&h0; u.y = *(uint32_t*)&h1;
        u.z = *(uint32_t*)&h2; u.w = *(uint32_t*)&h3;
        *(uint4*)(sA + r*128 + ((jj ^ (r & 7)) << 4)) = u;
    }
    __syncthreads();

    // ---- MMA: warp = 32 rows x 96 cols; 3 k16 groups ----
    float acc[2][12][4];
    #pragma unroll
    for (int i = 0; i < 2; i++)
        #pragma unroll
        for (int j = 0; j < 12; j++)
            #pragma unroll
            for (int q = 0; q < 4; q++) acc[i][j][q] = 0.f;

    int lrow = lane & 15, lc = lane >> 4;
    #pragma unroll
    for (int g = 0; g < 3; g++) {
        int ch = g*2 + lc;
        uint32_t a[2][4];
        #pragma unroll
        for (int mi = 0; mi < 2; mi++) {
            int row = wid*32 + mi*16 + lrow;
            LDSM4(a[mi], sb + (uint32_t)(row*128 + (((ch ^ (row & 7))) << 4)));
        }
        #pragma unroll
        for (int nb = 0; nb < 6; nb++) {
            int rowb = nb*16 + lrow;
            uint32_t bh[4];
            LDSM4(bh, sb + 16384u + (uint32_t)(rowb*128 + (((ch ^ (rowb & 7))) << 4)));
            #pragma unroll
            for (int mi = 0; mi < 2; mi++) {
                MMA16816(acc[mi][2*nb],   a[mi], bh[0], bh[2]);
                MMA16816(acc[mi][2*nb+1], a[mi], bh[1], bh[3]);
            }
        }
    }

    // ---- epilogue: BN1 + LeakyReLU -> g_hh fp16 NHWC ----
    #pragma unroll
    for (int mi = 0; mi < 2; mi++) {
        int r0 = bm + wid*32 + mi*16 + (lane >> 2);
        #pragma unroll
        for (int nj = 0; nj < 12; nj++) {
            int col = nj*8 + (lane & 3)*2;
            float s0 = sScale[col], s1 = sScale[col+1];
            float e0 = sBeta[col],  e1 = sBeta[col+1];
            float v0 = acc[mi][nj][0]*s0 + e0;
            float v1 = acc[mi][nj][1]*s1 + e1;
            float v2 = acc[mi][nj][2]*s0 + e0;
            float v3 = acc[mi][nj][3]*s1 + e1;
            v0 = (v0 >= 0.f) ? v0 : 0.01f*v0;
            v1 = (v1 >= 0.f) ? v1 : 0.01f*v1;
            v2 = (v2 >= 0.f) ? v2 : 0.01f*v2;
            v3 = (v3 >= 0.f) ? v3 : 0.01f*v3;
            __half2 ha = __floats2half2_rn(v0, v1);
            __half2 hbv = __floats2half2_rn(v2, v3);
            *(__half2*)&g_hh[(size_t)r0*CH + col]     = ha;
            *(__half2*)&g_hh[(size_t)(r0+8)*CH + col] = hbv;
        }
    }
}

// =====================================================================
// Kernel 2: weight prep (dcn_w fp16, off_w fp16, both [n][k*96+c])
// =====================================================================
__global__ __launch_bounds__(256) void prep_kernel(
    const float* __restrict__ wd, const float* __restrict__ wo)
{
    int i = blockIdx.x*256 + threadIdx.x;
    if (i < ND*KDIM) {
        int o = i / KDIM, r = i % KDIM;
        int k = r / CH, c = r % CH;
        g_Bhi[i] = __float2half(wd[(size_t)o*KDIM + c*16 + k]);
    }
    if (i < NOFF*KDIM) {
        int n = i / KDIM, r = i % KDIM;
        int k = r / CH, c = r % CH;
        g_woh[i] = __float2half(wo[(size_t)n*KDIM + c*16 + k]);
    }
}

// =====================================================================
// Kernel 3: offset conv via mma.sync, single-pass fp16
// =====================================================================
#define OC_NIT 48
#define OC_STG 6144u     // Ah 4K | Wh 2K
#define SMEM_OC (4*OC_STG)

__global__ __launch_bounds__(128, 1) void offconv_mma_kernel(const float* __restrict__ offb)
{
    extern __shared__ char smem[];
    uint32_t sb = smem_to_u32(smem);
    int tid = threadIdx.x;
    int lane = tid & 31, wid = tid >> 5;
    int bm = blockIdx.x * 64;

    int c4 = tid & 3;
    int r0 = tid >> 2, r1 = r0 + 32;
    int m0 = bm + r0, m1v = bm + r1;
    int b0 = m0 / SPA, s0 = m0 % SPA;
    int b1 = m1v / SPA, s1 = m1v % SPA;
    size_t rb0 = ((size_t)(b0*HH + (s0/HO)*4)*HH + (s0%HO)*4)*CH;
    size_t rb1 = ((size_t)(b1*HH + (s1/HO)*4)*HH + (s1%HO)*4)*CH;
    uint32_t so0 = (uint32_t)(r0*64 + ((c4 ^ ((r0>>1)&3))*16));
    uint32_t so1 = (uint32_t)(r1*64 + ((c4 ^ ((r1>>1)&3))*16));
    int wrow = tid >> 2;
    uint32_t sow = (uint32_t)(wrow*64 + ((c4 ^ ((wrow>>1)&3))*16));
    size_t wg = (size_t)wrow*KDIM + c4*8;

    auto load_stage = [&](int stg, int kt) {
        uint32_t base = sb + (uint32_t)stg * OC_STG;
        int kpix = kt / 3;
        int poff = (kpix >> 2)*(HH*CH) + (kpix & 3)*CH + (kt - kpix*3)*32 + c4*8;
        CP_ASYNC16(base + so0,        g_hh + rb0 + poff);
        CP_ASYNC16(base + so1,        g_hh + rb1 + poff);
        CP_ASYNC16(base + 4096 + sow, g_woh + wg + kt*32);
        CP_COMMIT();
    };

    int lrow = lane & 15, lc = lane >> 4;
    uint32_t a_off[2], w_off[2][2];
    #pragma unroll
    for (int kh = 0; kh < 2; kh++) {
        int row = wid*16 + lrow;
        a_off[kh] = (uint32_t)(row*64 + (((kh*2 + lc) ^ ((row>>1)&3))*16));
        #pragma unroll
        for (int h = 0; h < 2; h++) {
            int wr2 = h*16 + lrow;
            w_off[h][kh] = (uint32_t)(wr2*64 + (((kh*2 + lc) ^ ((wr2>>1)&3))*16));
        }
    }

    float acc[4][4];
    #pragma unroll
    for (int i = 0; i < 4; i++)
        #pragma unroll
        for (int q = 0; q < 4; q++) acc[i][q] = 0.f;

    load_stage(0, 0); load_stage(1, 1); load_stage(2, 2);

    for (int kt = 0; kt < OC_NIT; kt++) {
        if (kt + 2 < OC_NIT) asm volatile("cp.async.wait_group 2;" ::: "memory");
        else                 asm volatile("cp.async.wait_group 0;" ::: "memory");
        __syncthreads();
        if (kt + 3 < OC_NIT) load_stage((kt+3) & 3, kt+3);

        uint32_t base = sb + (uint32_t)(kt & 3) * OC_STG;
        #pragma unroll
        for (int kh = 0; kh < 2; kh++) {
            uint32_t ah[4];
            LDSM4(ah, base + a_off[kh]);
            #pragma unroll
            for (int h = 0; h < 2; h++) {
                uint32_t wh[4];
                LDSM4(wh, base + 4096 + w_off[h][kh]);
                MMA16816(acc[h*2],   ah, wh[0], wh[2]);
                MMA16816(acc[h*2+1], ah, wh[1], wh[3]);
            }
        }
    }

    int rr = bm + wid*16 + (lane >> 2);
    #pragma unroll
    for (int nj = 0; nj < 4; nj++) {
        int col = (nj >> 1)*16 + (nj & 1)*8 + (lane & 3)*2;
        float b0v = offb[col], b1v = offb[col+1];
        *(float2*)&g_off[(size_t)rr*NOFF + col] =
            make_float2(acc[nj][0] + b0v, acc[nj][1] + b1v);
        *(float2*)&g_off[(size_t)(rr+8)*NOFF + col] =
            make_float2(acc[nj][2] + b0v, acc[nj][3] + b1v);
    }
}

// =====================================================================
// Kernel 4: bilinear sampling (fp16 src) -> fp16 A [m][k*96+c]
// =====================================================================
__global__ __launch_bounds__(256) void sample_kernel()
{
    int m    = (blockIdx.x*256 + threadIdx.x) >> 5;
    int lane = threadIdx.x & 31;
    int b = m / SPA, s = m % SPA;
    int oh = s / HO, ow = s % HO;

    int e00 = 0, e01 = 0, e10 = 0, e11 = 0;
    float w00 = 0.f, w01 = 0.f, w10 = 0.f, w11 = 0.f;
    if (lane < 16) {
        int k = lane;
        float offy = g_off[(size_t)m*NOFF + k*2];
        float offx = g_off[(size_t)m*NOFF + k*2 + 1];
        float py = (float)(oh*4 + (k >> 2)) + offy;
        float px = (float)(ow*4 + (k & 3)) + offx;
        float y0f = floorf(py), x0f = floorf(px);
        float wy = py - y0f, wx = px - x0f;
        int y0 = (int)y0f, x0 = (int)x0f;
        int y1 = y0 + 1,  x1 = x0 + 1;
        bool vy0 = (y0 >= 0) & (y0 < HH), vy1 = (y1 >= 0) & (y1 < HH);
        bool vx0 = (x0 >= 0) & (x0 < HH), vx1 = (x1 >= 0) & (x1 < HH);
        int cy0 = min(max(y0, 0), HH-1), cy1 = min(max(y1, 0), HH-1);
        int cx0 = min(max(x0, 0), HH-1), cx1 = min(max(x1, 0), HH-1);
        e00 = (cy0*HH + cx0)*CH;
        e01 = (cy0*HH + cx1)*CH;
        e10 = (cy1*HH + cx0)*CH;
        e11 = (cy1*HH + cx1)*CH;
        w00 = (1.f-wy)*(1.f-wx) * (float)(vy0 && vx0);
        w01 = (1.f-wy)*wx       * (float)(vy0 && vx1);
        w10 = wy*(1.f-wx)       * (float)(vy1 && vx0);
        w11 = wy*wx             * (float)(vy1 && vx1);
    }

    const __half* hb = g_hh + (size_t)b*HH*HH*CH;
    __half* ob = g_Af + (size_t)m*KDIM;
    int c = (lane < 24) ? lane*4 : 0;

    #pragma unroll 4
    for (int k = 0; k < 16; k++) {
        int   f00 = __shfl_sync(0xFFFFFFFFu, e00, k);
        int   f01 = __shfl_sync(0xFFFFFFFFu, e01, k);
        int   f10 = __shfl_sync(0xFFFFFFFFu, e10, k);
        int   f11 = __shfl_sync(0xFFFFFFFFu, e11, k);
        float q00 = __shfl_sync(0xFFFFFFFFu, w00, k);
        float q01 = __shfl_sync(0xFFFFFFFFu, w01, k);
        float q10 = __shfl_sync(0xFFFFFFFFu, w10, k);
        float q11 = __shfl_sync(0xFFFFFFFFu, w11, k);
        if (lane < 24) {
            uint2 u00 = *(const uint2*)(hb + f00 + c);
            uint2 u01 = *(const uint2*)(hb + f01 + c);
            uint2 u10 = *(const uint2*)(hb + f10 + c);
            uint2 u11 = *(const uint2*)(hb + f11 + c);
            float2 a0 = __half22float2(*(__half2*)&u00.x);
            float2 a1 = __half22float2(*(__half2*)&u00.y);
            float2 b0 = __half22float2(*(__half2*)&u01.x);
            float2 b1 = __half22float2(*(__half2*)&u01.y);
            float2 c0 = __half22float2(*(__half2*)&u10.x);
            float2 c1 = __half22float2(*(__half2*)&u10.y);
            float2 d0 = __half22float2(*(__half2*)&u11.x);
            float2 d1 = __half22float2(*(__half2*)&u11.y);
            float r0 = a0.x*q00 + b0.x*q01 + c0.x*q10 + d0.x*q11;
            float r1 = a0.y*q00 + b0.y*q01 + c0.y*q10 + d0.y*q11;
            float r2 = a1.x*q00 + b1.x*q01 + c1.x*q10 + d1.x*q11;
            float r3 = a1.y*q00 + b1.y*q01 + c1.y*q10 + d1.y*q11;
            __half2 h0 = __floats2half2_rn(r0, r1);
            __half2 h1 = __floats2half2_rn(r2, r3);
            uint2 o;
            o.x = *(uint32_t*)&h0;
            o.y = *(uint32_t*)&h1;
            *(uint2*)(ob + k*CH + c) = o;
        }
    }
}

// =====================================================================
// Kernel 5: single-pass fp16 GEMM + BN2 + LeakyReLU
// CTA 128x128, BK=64, 8 warps (warp 64x32), 3-stage cp.async, 2 CTA/SM
// =====================================================================
#define BK       64
#define NIT      24
#define OFF_B    16384u
#define STG_BYTES 32768u
#define NSTAGE   3
#define SMEM_GEMM (NSTAGE*STG_BYTES + 1024)

__global__ __launch_bounds__(256, 2) void gemm_mma_kernel(
    const float* __restrict__ dcnb, const float* __restrict__ g2,
    const float* __restrict__ b2,   const float* __restrict__ bn2m,
    const float* __restrict__ v2,   float* __restrict__ out)
{
    extern __shared__ char smem[];
    uint32_t sb = smem_to_u32(smem);
    float* sScale = (float*)(smem + NSTAGE*STG_BYTES);
    float* sBeta  = sScale + 128;

    int tid  = threadIdx.x;
    int lane = tid & 31, wid = tid >> 5;
    int wm = wid & 1, wn = wid >> 1;
    int bm = blockIdx.y * 128;
    int bn = blockIdx.x * 128;

    if (tid < 128) {
        int n = bn + tid;
        float inv = g2[n] * rsqrtf(v2[n] + 1e-5f);
        sScale[tid] = inv;
        sBeta[tid]  = (dcnb[n] - bn2m[n])*inv + b2[n];
    }

    auto load_stage = [&](int stg, int kt) {
        uint32_t base = sb + (uint32_t)stg * STG_BYTES;
        int ks = kt * BK;
        #pragma unroll
        for (int i = 0; i < 4; i++) {
            int id = tid + i*256;
            int row = id >> 3, c = id & 7;
            uint32_t so = (uint32_t)(row*128 + ((c ^ (row & 7))*16));
            CP_ASYNC16(base + so, g_Af + (size_t)(bm+row)*KDIM + ks + c*8);
        }
        #pragma unroll
        for (int i = 0; i < 4; i++) {
            int id = tid + i*256;
            int row = id >> 3, c = id & 7;
            uint32_t so = (uint32_t)(row*128 + ((c ^ (row & 7))*16));
            CP_ASYNC16(base + OFF_B + so, g_Bhi + (size_t)(bn+row)*KDIM + ks + c*8);
        }
        CP_COMMIT();
    };

    int lrow = lane & 15, lc = lane >> 4;
    uint32_t a_base[4]; int a_rs[4];
    uint32_t b_base[2]; int b_rs[2];
    #pragma unroll
    for (int mi = 0; mi < 4; mi++) {
        int row = wm*64 + mi*16 + lrow;
        a_base[mi] = (uint32_t)(row*128);
        a_rs[mi]   = row & 7;
    }
    #pragma unroll
    for (int nb = 0; nb < 2; nb++) {
        int row = wn*32 + nb*16 + lrow;
        b_base[nb] = (uint32_t)(row*128);
        b_rs[nb]   = row & 7;
    }

    float acc[4][4][4];
    #pragma unroll
    for (int i = 0; i < 4; i++)
        #pragma unroll
        for (int j = 0; j < 4; j++)
            #pragma unroll
            for (int q = 0; q < 4; q++) acc[i][j][q] = 0.f;

    load_stage(0, 0); load_stage(1, 1);

    for (int kt = 0; kt < NIT; kt++) {
        if (kt + 1 < NIT) asm volatile("cp.async.wait_group 1;" ::: "memory");
        else              asm volatile("cp.async.wait_group 0;" ::: "memory");
        __syncthreads();
        if (kt + 2 < NIT) load_stage((kt+2) % NSTAGE, kt+2);

        uint32_t base = sb + (uint32_t)(kt % NSTAGE) * STG_BYTES;
        #pragma unroll
        for (int kh = 0; kh < 4; kh++) {
            int ch = kh*2 + lc;
            uint32_t a[4][4];
            #pragma unroll
            for (int mi = 0; mi < 4; mi++)
                LDSM4(a[mi], base + a_base[mi] + (uint32_t)(((ch ^ a_rs[mi]) << 4)));
            #pragma unroll
            for (int nb = 0; nb < 2; nb++) {
                uint32_t bh[4];
                LDSM4(bh, base + OFF_B + b_base[nb] + (uint32_t)(((ch ^ b_rs[nb]) << 4)));
                #pragma unroll
                for (int mi = 0; mi < 4; mi++) {
                    MMA16816(acc[mi][2*nb],   a[mi], bh[0], bh[2]);
                    MMA16816(acc[mi][2*nb+1], a[mi], bh[1], bh[3]);
                }
            }
        }
    }

    #pragma unroll
    for (int mi = 0; mi < 4; mi++) {
        int r0 = bm + wm*64 + mi*16 + (lane >> 2);
        #pragma unroll
        for (int nj = 0; nj < 4; nj++) {
            int colL = wn*32 + nj*8 + (lane & 3)*2;
            float s0 = sScale[colL],   s1 = sScale[colL+1];
            float e0 = sBeta[colL],    e1 = sBeta[colL+1];
            float v0 = acc[mi][nj][0]*s0 + e0;
            float v1 = acc[mi][nj][1]*s1 + e1;
            float v2 = acc[mi][nj][2]*s0 + e0;
            float v3 = acc[mi][nj][3]*s1 + e1;
            v0 = (v0 >= 0.f) ? v0 : 0.01f*v0;
            v1 = (v1 >= 0.f) ? v1 : 0.01f*v1;
            v2 = (v2 >= 0.f) ? v2 : 0.01f*v2;
            v3 = (v3 >= 0.f) ? v3 : 0.01f*v3;
            *(float2*)&out[(size_t)r0*ND + bn + colL]     = make_float2(v0, v1);
            *(float2*)&out[(size_t)(r0+8)*ND + bn + colL] = make_float2(v2, v3);
        }
    }
}

// =====================================================================
extern "C" void kernel_launch(void* const* d_in, const int* in_sizes, int n_in,
                              void* d_out, int out_size)
{
    const float* x      = (const float*)d_in[0];
    const float* stem_w = (const float*)d_in[1];
    const float* stem_b = (const float*)d_in[2];
    const float* bn1_g  = (const float*)d_in[3];
    const float* bn1_b  = (const float*)d_in[4];
    const float* bn1_m  = (const float*)d_in[5];
    const float* bn1_v  = (const float*)d_in[6];
    const float* off_w  = (const float*)d_in[7];
    const float* off_b  = (const float*)d_in[8];
    const float* dcn_w  = (const float*)d_in[9];
    const float* dcn_b  = (const float*)d_in[10];
    const float* bn2_g  = (const float*)d_in[11];
    const float* bn2_b  = (const float*)d_in[12];
    const float* bn2_m  = (const float*)d_in[13];
    const float* bn2_v  = (const float*)d_in[14];
    float* out = (float*)d_out;

    cudaFuncSetAttribute(gemm_mma_kernel,
                         cudaFuncAttributeMaxDynamicSharedMemorySize, SMEM_GEMM);
    cudaFuncSetAttribute(offconv_mma_kernel,
                         cudaFuncAttributeMaxDynamicSharedMemorySize, SMEM_OC);
    cudaFuncSetAttribute(stem_mma_kernel,
                         cudaFuncAttributeMaxDynamicSharedMemorySize, SMEM_ST);

    stem_mma_kernel<<<(NB*SH)/128, 128, SMEM_ST>>>(
        x, stem_w, stem_b, bn1_g, bn1_b, bn1_m, bn1_v);
    prep_kernel<<<(ND*KDIM + 255)/256, 256>>>(dcn_w, off_w);
    offconv_mma_kernel<<<MM2/64, 128, SMEM_OC>>>(off_b);
    sample_kernel<<<MM2*32/256, 256>>>();
    gemm_mma_kernel<<<dim3(ND/128, MM2/128), 256, SMEM_GEMM>>>(
        dcn_b, bn2_g, bn2_b, bn2_m, bn2_v, out);
}